// round 9
// baseline (speedup 1.0000x reference)
#include <cuda_runtime.h>
#include <cstdint>

#define C_DIM 1024
#define B_SZ  4
#define W_LEN 4096
#define NHD   8
#define KD    64
#define HD    128
#define L2C   4096
#define L3C   6561
#define L3P   6656
#define NBH   (B_SZ*NHD)
#define SCALE 0.125f

__device__ float    g_q   [NBH * L3C * KD];
__device__ float    g_k   [NBH * L3C * KD];
__device__ float    g_v0  [NBH * L3C * HD];
__device__ float    g_wa  [NBH * L3C * HD];
__device__ float    g_wb  [NBH * L3C * HD];
__device__ float    g_attn[5038848];
__device__ float    g_x1  [B_SZ * C_DIM * W_LEN];   // f32 residual (channel-major)
__device__ uint32_t g_xtf [B_SZ * C_DIM * W_LEN];   // tf32 bits: x, later x2
__device__ uint32_t g_x1tf[B_SZ * C_DIM * L3P];     // tf32 bits: x1 padded rows
__device__ uint32_t g_wp  [2048 * C_DIM];           // tf32 bits, k-permuted W

__device__ __forceinline__ uint32_t f2tf(float f) {
    uint32_t u; asm("cvt.rna.tf32.f32 %0, %1;" : "=r"(u) : "f"(f)); return u;
}

// ---------------------------------------------------------------------------
// Convert + merge + k-permute weights.
// Within each 32-k chunk: kp = ks*8 + (k&3)*2 + ((k>>2)&1), ks = k>>3.
// ---------------------------------------------------------------------------
__global__ void conv_w(const float* __restrict__ w0, const float* __restrict__ w1,
                       uint32_t* __restrict__ wp, int rows0, int total)
{
    int idx = blockIdx.x * 256 + threadIdx.x;
    if (idx >= total) return;
    int o = idx >> 10, kg = idx & 1023;
    int k = kg & 31, kb = kg >> 5;
    int kp = ((k >> 3) << 3) + ((k & 3) << 1) + ((k >> 2) & 1);
    const float* src = (o < rows0) ? (w0 + (size_t)o * C_DIM)
                                   : (w1 + (size_t)(o - rows0) * C_DIM);
    wp[(size_t)o * C_DIM + (kb << 5) + kp] = f2tf(src[kg]);
}

// elementwise f32 -> tf32 bits
__global__ void conv_x(const float* __restrict__ x, uint32_t* __restrict__ y, int n) {
    int i = blockIdx.x * 256 + threadIdx.x;
    if (i < n) y[i] = f2tf(x[i]);
}

// zero the padding rows of x1tf: l in [W_LEN, L3P) for every (b, c)
__global__ void pad_x1tf(uint32_t* __restrict__ y) {
    int i = blockIdx.x * 256 + threadIdx.x;           // over 4*1024*2560
    int bc = i / (L3P - W_LEN), r = i % (L3P - W_LEN);
    y[(size_t)bc * L3P + W_LEN + r] = 0u;
}

// ---------------------------------------------------------------------------
// tf32 mma.sync GEMM, operands pre-converted (u32 tf32 bits).
// 256x128x32 CTA tiles, 8 warps of 64x64, 3-stage cp.async pipeline,
// ONE barrier per k-iteration.
// ASTR=40: 16B-aligned cp.async AND conflict-free A-fragment LDS.64.
// MODE 0: M=2048 (qk rows<1024, v rows>=1024), scatter pos-major q/k/v.
// MODE 1: M=1024 proj, channel-major out via qbuf.
// ---------------------------------------------------------------------------
template<int MODE>
__launch_bounds__(256)
__global__ void gemm_tc(const uint32_t* __restrict__ xtf, int XROW,
                        const uint32_t* __restrict__ wp,
                        const float* __restrict__ s0, const float* __restrict__ b0,
                        const float* __restrict__ s1, const float* __restrict__ b1,
                        float* __restrict__ qbuf, float* __restrict__ kbuf,
                        float* __restrict__ vbuf, int L)
{
    extern __shared__ float smf[];
    uint32_t* sm = (uint32_t*)smf;
    constexpr int ASTR = 40;    // 256 x 32 A tile, stride 40 words (160B rows)
    constexpr int BSTR = 136;   // 32 x 128 B tile, stride 136 (conflict-free)
    constexpr int AWORDS = 256 * ASTR;   // 10240
    constexpr int BWORDS = 32 * BSTR;    // 4352
    uint32_t* Asm[3] = { sm, sm + AWORDS, sm + 2*AWORDS };
    uint32_t* Bsm[3] = { sm + 3*AWORDS, sm + 3*AWORDS + BWORDS, sm + 3*AWORDS + 2*BWORDS };

    const int tid  = threadIdx.x;
    const int lane = tid & 31, warp = tid >> 5;
    const int wm = warp >> 1, wn = warp & 1;         // warp grid 4 x 2, tile 64x64
    const int grp = lane >> 2, qid = lane & 3;
    const int l0 = blockIdx.x * 128, o0 = blockIdx.y * 256, bz = blockIdx.z;

    const uint32_t* wmat = wp + (size_t)o0 * C_DIM;
    const bool alt = (MODE == 0) && (o0 >= 1024);
    const float* sptr = alt ? (s1 + (o0 - 1024)) : (s0 + o0);
    const float* bptr = alt ? (b1 + (o0 - 1024)) : (b0 + o0);
    const uint32_t* xbase = xtf + (size_t)bz * C_DIM * XROW;

    const int am = tid >> 3, ak = (tid & 7) * 4;   // A: rows am+32i (i<8), col ak
    const int bk = tid >> 5, bl = (tid & 31) * 4;  // B: rows bk+8i (i<4), col bl
    const int lg = l0 + bl;

    float acc[4][8][4] = {};

    auto load_tile = [&](int buf, int c0) {
        #pragma unroll
        for (int i = 0; i < 8; i++) {
            uint32_t d = (uint32_t)__cvta_generic_to_shared(&Asm[buf][(am + 32*i) * ASTR + ak]);
            const uint32_t* s = wmat + (size_t)(am + 32*i) * C_DIM + c0 + ak;
            asm volatile("cp.async.ca.shared.global [%0], [%1], 16;\n" :: "r"(d), "l"(s));
        }
        #pragma unroll
        for (int i = 0; i < 4; i++) {
            uint32_t d = (uint32_t)__cvta_generic_to_shared(&Bsm[buf][(bk + 8*i) * BSTR + bl]);
            const uint32_t* s = xbase + (size_t)(c0 + bk + 8*i) * XROW + lg;
            asm volatile("cp.async.ca.shared.global [%0], [%1], 16;\n" :: "r"(d), "l"(s));
        }
        asm volatile("cp.async.commit_group;\n");
    };

    // 3-stage prologue: stages 0 and 1 in flight
    load_tile(0, 0);
    load_tile(1, 32);

    int cur = 0, nxt = 2;                     // nxt = (kt+2) % 3
    for (int kt = 0; kt < 32; ++kt) {
        if (kt < 31) asm volatile("cp.async.wait_group 1;\n");
        else         asm volatile("cp.async.wait_group 0;\n");
        __syncthreads();
        if (kt + 2 < 32) load_tile(nxt, (kt + 2) * 32);

        const uint32_t* Ab = Asm[cur];
        const uint32_t* Bb = Bsm[cur];
        #pragma unroll
        for (int ks = 0; ks < 4; ++ks) {
            uint32_t bf[8][2];
            #pragma unroll
            for (int nt = 0; nt < 8; ++nt) {
                const uint32_t* bp = Bb + (ks*8 + qid) * BSTR + wn*64 + nt*8 + grp;
                bf[nt][0] = bp[0];
                bf[nt][1] = bp[4 * BSTR];
            }
            #pragma unroll
            for (int mt = 0; mt < 4; ++mt) {
                // {a0,a2} contiguous at row*ASTR + ks*8 + qid*2
                const int base = (wm*64 + mt*16 + grp) * ASTR + ks*8 + qid*2;
                uint2 lo = *(const uint2*)&Ab[base];            // a0, a2 (row grp)
                uint2 hi = *(const uint2*)&Ab[base + 8*ASTR];   // a1, a3 (row grp+8)
                #pragma unroll
                for (int nt = 0; nt < 8; ++nt) {
                    float* d = acc[mt][nt];
                    asm volatile(
                        "mma.sync.aligned.m16n8k8.row.col.f32.tf32.tf32.f32 "
                        "{%0,%1,%2,%3},{%4,%5,%6,%7},{%8,%9},{%0,%1,%2,%3};\n"
                        : "+f"(d[0]), "+f"(d[1]), "+f"(d[2]), "+f"(d[3])
                        : "r"(lo.x), "r"(hi.x), "r"(lo.y), "r"(hi.y),
                          "r"(bf[nt][0]), "r"(bf[nt][1]));
                }
            }
        }
        cur = (cur == 2) ? 0 : cur + 1;
        nxt = (nxt == 2) ? 0 : nxt + 1;
    }
    __syncthreads();

    // ---- epilogue via SMEM staging ----
    float* ep = smf;
    constexpr int EPS = (MODE == 0) ? 260 : 132;
    #pragma unroll
    for (int mt = 0; mt < 4; ++mt)
        #pragma unroll
        for (int nt = 0; nt < 8; ++nt) {
            int ol = wm*64 + mt*16 + grp;
            int ll = wn*64 + nt*8 + 2*qid;
            float* c = acc[mt][nt];
            if (MODE == 0) {             // ep[l][o]: 128 x 260
                ep[ll * EPS + ol]           = c[0];
                ep[(ll + 1) * EPS + ol]     = c[1];
                ep[ll * EPS + ol + 8]       = c[2];
                ep[(ll + 1) * EPS + ol + 8] = c[3];
            } else {                     // ep[o][l]: 256 x 132
                ep[ol * EPS + ll]           = c[0];
                ep[ol * EPS + ll + 1]       = c[1];
                ep[(ol + 8) * EPS + ll]     = c[2];
                ep[(ol + 8) * EPS + ll + 1] = c[3];
            }
        }
    __syncthreads();

    if (MODE == 0) {
        for (int f = tid; f < 8192; f += 256) {
            int l = f >> 6, o4 = (f & 63) << 2;
            int lgl = l0 + l;
            if (lgl >= L) continue;
            float4 v  = *(float4*)&ep[l * EPS + o4];
            float4 s4 = *(const float4*)(sptr + o4);
            float4 b4 = *(const float4*)(bptr + o4);
            float4 r = make_float4(v.x*s4.x + b4.x, v.y*s4.y + b4.y,
                                   v.z*s4.z + b4.z, v.w*s4.w + b4.w);
            int og = o0 + o4;
            float* dst;
            if (o0 < 1024) {
                int h = og >> 7, rr = (og >> 6) & 1, d0 = og & 63;
                dst = (rr ? kbuf : qbuf) + ((size_t)(bz * NHD + h) * L + lgl) * KD + d0;
            } else {
                int oc = og - 1024, h = oc >> 7, d0 = oc & 127;
                dst = vbuf + ((size_t)(bz * NHD + h) * L + lgl) * HD + d0;
            }
            *(float4*)dst = r;
        }
    } else {
        for (int f = tid; f < 8192; f += 256) {
            int o = f >> 5, l4 = (f & 31) << 2;
            float4 v = *(float4*)&ep[o * EPS + l4];
            float sc = sptr[o], bi = bptr[o];
            float4 r = make_float4(v.x*sc + bi, v.y*sc + bi, v.z*sc + bi, v.w*sc + bi);
            *(float4*)(qbuf + ((size_t)(bz * C_DIM + o0 + o)) * W_LEN + l0 + l4) = r;
        }
    }
}

// ---------------------------------------------------------------------------
// Precompute softmaxed base x base attention matrices per level.
// ---------------------------------------------------------------------------
template<int BASE, int T, int NE, bool INNER>
__launch_bounds__(256)
__global__ void attn_kernel(const float* __restrict__ q, const float* __restrict__ k,
                            float* __restrict__ attn, int L)
{
    constexpr int GT = T / BASE;
    constexpr int BB = BASE * BASE;
    __shared__ float qs[T * KD];
    __shared__ float ks[T * KD];
    __shared__ float ls[GT * BB];
    const int tile = blockIdx.x, bh = blockIdx.y, tid = threadIdx.x;

    if (INNER) {
        size_t gb = ((size_t)bh * L + (size_t)tile * T) * KD;
        const float4* q4 = (const float4*)(q + gb);
        const float4* k4 = (const float4*)(k + gb);
        for (int i = tid; i < T * KD / 4; i += 256) {
            ((float4*)qs)[i] = q4[i]; ((float4*)ks)[i] = k4[i];
        }
    } else {
        for (int i = tid; i < T * (KD/4); i += 256) {
            int p = i / (KD/4), dq = i % (KD/4);
            size_t gb = ((size_t)bh * L + (size_t)p * T + tile) * KD;
            ((float4*)qs)[i] = *((const float4*)(q + gb) + dq);
            ((float4*)ks)[i] = *((const float4*)(k + gb) + dq);
        }
    }
    __syncthreads();

    int s = 1;
    #pragma unroll
    for (int e = 0; e < NE; e++) {
        for (int it = tid; it < GT * BB; it += 256) {
            int g = it / BB, rem = it % BB;
            int J = rem / BASE, j = rem % BASE;
            int hi = g / s, lo = g % s;
            int pJ = hi * BASE * s + J * s + lo;
            int pj = hi * BASE * s + j * s + lo;
            const float4* qp = (const float4*)(qs + pj * KD);
            const float4* kp = (const float4*)(ks + pJ * KD);
            float dot = 0.f;
            #pragma unroll
            for (int dd = 0; dd < KD/4; dd++) {
                float4 a = qp[dd], b2 = kp[dd];
                dot += a.x*b2.x + a.y*b2.y + a.z*b2.z + a.w*b2.w;
            }
            ls[it] = dot * SCALE;
        }
        __syncthreads();
        const int eg = e + (INNER ? 0 : NE);
        size_t lvl = ((size_t)eg * NBH + bh) * (size_t)(L / BASE) * BB;
        for (int it = tid; it < GT * BASE; it += 256) {
            int g = it / BASE, J = it % BASE;
            const float* lg2 = ls + (g * BASE + J) * BASE;
            float m = lg2[0];
            #pragma unroll
            for (int j = 1; j < BASE; j++) m = fmaxf(m, lg2[j]);
            float ex[BASE]; float sum = 0.f;
            #pragma unroll
            for (int j = 0; j < BASE; j++) { ex[j] = __expf(lg2[j] - m); sum += ex[j]; }
            float inv = 1.f / sum;
            size_t gg = INNER ? ((size_t)tile * GT + g) : ((size_t)g * T + tile);
            float* ap = attn + lvl + gg * BB + (size_t)J * BASE;
            #pragma unroll
            for (int j = 0; j < BASE; j++) ap[j] = ex[j] * inv;
        }
        __syncthreads();
        s *= BASE;
    }
}

// ---------------------------------------------------------------------------
// Apply NE levels to v inside SMEM (one global read + write per pass).
// ---------------------------------------------------------------------------
template<int BASE, int T, int NE, bool INNER, bool ASC>
__launch_bounds__(256)
__global__ void stage_kernel(const float* __restrict__ vin, float* __restrict__ vout,
                             const float* __restrict__ attn, int L)
{
    constexpr int GT = T / BASE;
    constexpr int BB = BASE * BASE;
    __shared__ float vs[T * HD];
    __shared__ float as_[GT * BB];
    const int tile = blockIdx.x, bh = blockIdx.y, tid = threadIdx.x;

    if (INNER) {
        size_t gb = ((size_t)bh * L + (size_t)tile * T) * HD;
        const float4* v4 = (const float4*)(vin + gb);
        for (int i = tid; i < T * HD / 4; i += 256) ((float4*)vs)[i] = v4[i];
    } else {
        for (int i = tid; i < T * (HD/4); i += 256) {
            int p = i / (HD/4), dq = i % (HD/4);
            ((float4*)vs)[i] = *((const float4*)(vin + ((size_t)bh * L + (size_t)p * T + tile) * HD) + dq);
        }
    }
    __syncthreads();

    #pragma unroll
    for (int step = 0; step < NE; step++) {
        const int e = ASC ? step : (NE - 1 - step);
        int s = 1;
        #pragma unroll
        for (int t2 = 0; t2 < NE; t2++) if (t2 < e) s *= BASE;
        const int eg = e + (INNER ? 0 : NE);
        size_t lvl = ((size_t)eg * NBH + bh) * (size_t)(L / BASE) * BB;
        for (int it = tid; it < GT * BB; it += 256) {
            int g = it / BB, c = it % BB;
            size_t gg = INNER ? ((size_t)tile * GT + g) : ((size_t)g * T + tile);
            as_[it] = attn[lvl + gg * BB + c];
        }
        __syncthreads();
        for (int w = tid; w < GT * HD; w += 256) {
            int g = w >> 7, d = w & 127;
            int hi = g / s, lo = g - hi * s;
            int pb = hi * BASE * s + lo;
            float vv[BASE];
            #pragma unroll
            for (int j = 0; j < BASE; j++) vv[j] = vs[(pb + j * s) * HD + d];
            const float* ag = as_ + g * BB;
            #pragma unroll
            for (int J = 0; J < BASE; J++) {
                float o = 0.f;
                #pragma unroll
                for (int j = 0; j < BASE; j++) o += ag[J * BASE + j] * vv[j];
                vs[(pb + J * s) * HD + d] = o;
            }
        }
        __syncthreads();
    }

    if (INNER) {
        size_t gb = ((size_t)bh * L + (size_t)tile * T) * HD;
        float4* v4 = (float4*)(vout + gb);
        for (int i = tid; i < T * HD / 4; i += 256) v4[i] = ((float4*)vs)[i];
    } else {
        for (int i = tid; i < T * (HD/4); i += 256) {
            int p = i / (HD/4), dq = i % (HD/4);
            *((float4*)(vout + ((size_t)bh * L + (size_t)p * T + tile) * HD) + dq) = ((float4*)vs)[i];
        }
    }
}

// ---------------------------------------------------------------------------
// y = x + wa + wb + dwconv3(v0)*spe + bpe   (channel-major out, l < W only)
// Writes tf32 bits to ytf (row length YROW); if WF32, also writes f32 to yf.
// ---------------------------------------------------------------------------
template<bool WF32>
__launch_bounds__(256)
__global__ void combine_kernel(const float* __restrict__ xin,
                               const float* __restrict__ wa, const float* __restrict__ wb,
                               const float* __restrict__ v0,
                               const float* __restrict__ wpe, const float* __restrict__ spe,
                               const float* __restrict__ bpe,
                               float* __restrict__ yf, uint32_t* __restrict__ ytf,
                               int YROW, int L)
{
    __shared__ float s[32][129];
    __shared__ float v0s[34][129];
    const int bh = blockIdx.y;
    const int b = bh >> 3, h = bh & 7;
    const int l0 = blockIdx.x * 32;
    const int tid = threadIdx.x;

    size_t base = ((size_t)bh * L + l0) * HD;
    for (int i = tid; i < 32 * 128; i += 256) {
        int l = i >> 7, d = i & 127;
        s[l][d] = wa[base + (size_t)l * HD + d] + wb[base + (size_t)l * HD + d];
    }
    for (int i = tid; i < 34 * 128; i += 256) {
        int l = i >> 7, d = i & 127;
        int lg = l0 - 1 + l;
        float v = 0.f;
        if (lg >= 0 && lg < L) v = v0[((size_t)bh * L + lg) * HD + d];
        v0s[l][d] = v;
    }
    __syncthreads();

    const int lw = tid & 31, dw0 = tid >> 5;
    for (int dd = dw0; dd < 128; dd += 8) {
        int c = h * 128 + dd;
        float w0 = wpe[c*3+0], w1 = wpe[c*3+1], w2 = wpe[c*3+2];
        float sc = spe[c], bi = bpe[c];
        float pe = (w0 * v0s[lw][dd] + w1 * v0s[lw+1][dd] + w2 * v0s[lw+2][dd]) * sc + bi;
        size_t xi = ((size_t)b * C_DIM + c) * W_LEN + l0 + lw;
        float val = xin[xi] + s[lw][dd] + pe;
        if (WF32) yf[xi] = val;
        ytf[((size_t)b * C_DIM + c) * YROW + l0 + lw] = f2tf(val);
    }
}

// ---------------------------------------------------------------------------
extern "C" void kernel_launch(void* const* d_in, const int* in_sizes, int n_in,
                              void* d_out, int out_size)
{
    const float* x = (const float*)d_in[0];
    const float *wqk2=(const float*)d_in[1], *sqk2=(const float*)d_in[2], *bqk2=(const float*)d_in[3];
    const float *wv2 =(const float*)d_in[4], *sv2 =(const float*)d_in[5], *bv2 =(const float*)d_in[6];
    const float *wpe2=(const float*)d_in[7], *spe2=(const float*)d_in[8], *bpe2=(const float*)d_in[9];
    const float *wqk3=(const float*)d_in[10],*sqk3=(const float*)d_in[11],*bqk3=(const float*)d_in[12];
    const float *wv3 =(const float*)d_in[13],*sv3 =(const float*)d_in[14],*bv3 =(const float*)d_in[15];
    const float *wpe3=(const float*)d_in[16],*spe3=(const float*)d_in[17],*bpe3=(const float*)d_in[18];
    const float *wproj=(const float*)d_in[19],*sproj=(const float*)d_in[20],*bproj=(const float*)d_in[21];
    float* out = (float*)d_out;

    float *q, *k, *v0, *wa, *wb, *attn, *x1;
    uint32_t *xtf, *x1tf, *wp;
    cudaGetSymbolAddress((void**)&q,    g_q);
    cudaGetSymbolAddress((void**)&k,    g_k);
    cudaGetSymbolAddress((void**)&v0,   g_v0);
    cudaGetSymbolAddress((void**)&wa,   g_wa);
    cudaGetSymbolAddress((void**)&wb,   g_wb);
    cudaGetSymbolAddress((void**)&attn, g_attn);
    cudaGetSymbolAddress((void**)&x1,   g_x1);
    cudaGetSymbolAddress((void**)&xtf,  g_xtf);
    cudaGetSymbolAddress((void**)&x1tf, g_x1tf);
    cudaGetSymbolAddress((void**)&wp,   g_wp);

    const int SMEM = 175104;   // 3*(A 40960B) + 3*(B 17408B); epilogue reuses
    cudaFuncSetAttribute(gemm_tc<0>, cudaFuncAttributeMaxDynamicSharedMemorySize, SMEM);
    cudaFuncSetAttribute(gemm_tc<1>, cudaFuncAttributeMaxDynamicSharedMemorySize, SMEM);

    const int NX = B_SZ * C_DIM * W_LEN;
    conv_x<<<(NX + 255) / 256, 256>>>(x, xtf, NX);
    pad_x1tf<<<(B_SZ * C_DIM * (L3P - W_LEN)) / 256, 256>>>(x1tf);

    // ---- block 1: base=2, L=4096, NE=6, T=64 ----
    {
        const int L = L2C;
        conv_w<<<(2048 * 1024) / 256, 256>>>(wqk2, wv2, wp, 1024, 2048 * 1024);
        gemm_tc<0><<<dim3(32,8,4),256,SMEM>>>(xtf, W_LEN, wp, sqk2,bqk2, sv2,bv2, q,k,v0, L);
        attn_kernel<2,64,6,true ><<<dim3(64,NBH),256>>>(q,k,attn,L);
        attn_kernel<2,64,6,false><<<dim3(64,NBH),256>>>(q,k,attn,L);
        stage_kernel<2,64,6,true ,true ><<<dim3(64,NBH),256>>>(v0,wa,attn,L);
        stage_kernel<2,64,6,false,true ><<<dim3(64,NBH),256>>>(wa,wa,attn,L);
        stage_kernel<2,64,6,false,false><<<dim3(64,NBH),256>>>(v0,wb,attn,L);
        stage_kernel<2,64,6,true ,false><<<dim3(64,NBH),256>>>(wb,wb,attn,L);
        combine_kernel<true><<<dim3(128,NBH),256>>>(x, wa,wb,v0, wpe2,spe2,bpe2,
                                                    x1, x1tf, L3P, L);
    }
    // ---- block 2: base=3, L=6561, NE=4, T=81 ----
    {
        const int L = L3C;
        conv_w<<<(2048 * 1024) / 256, 256>>>(wqk3, wv3, wp, 1024, 2048 * 1024);
        gemm_tc<0><<<dim3(52,8,4),256,SMEM>>>(x1tf, L3P, wp, sqk3,bqk3, sv3,bv3, q,k,v0, L);
        attn_kernel<3,81,4,true ><<<dim3(81,NBH),256>>>(q,k,attn,L);
        attn_kernel<3,81,4,false><<<dim3(81,NBH),256>>>(q,k,attn,L);
        stage_kernel<3,81,4,true ,true ><<<dim3(81,NBH),256>>>(v0,wa,attn,L);
        stage_kernel<3,81,4,false,true ><<<dim3(81,NBH),256>>>(wa,wa,attn,L);
        stage_kernel<3,81,4,false,false><<<dim3(81,NBH),256>>>(v0,wb,attn,L);
        stage_kernel<3,81,4,true ,false><<<dim3(81,NBH),256>>>(wb,wb,attn,L);
        combine_kernel<false><<<dim3(128,NBH),256>>>(x1, wa,wb,v0, wpe3,spe3,bpe3,
                                                     nullptr, xtf, W_LEN, L);
    }
    // ---- final projection ----
    conv_w<<<(1024 * 1024) / 256, 256>>>(wproj, nullptr, wp, 1024, 1024 * 1024);
    gemm_tc<1><<<dim3(32,4,4),256,SMEM>>>(xtf, W_LEN, wp, sproj,bproj, nullptr,nullptr,
                                          out, nullptr, nullptr, W_LEN);
}

// round 10
// speedup vs baseline: 1.0538x; 1.0538x over previous
#include <cuda_runtime.h>
#include <cstdint>

#define C_DIM 1024
#define B_SZ  4
#define W_LEN 4096
#define NHD   8
#define KD    64
#define HD    128
#define L2C   4096
#define L3C   6561
#define L3P   6656
#define NBH   (B_SZ*NHD)
#define SCALE 0.125f

__device__ float    g_q   [NBH * L3C * KD];
__device__ float    g_k   [NBH * L3C * KD];
__device__ float    g_v0  [NBH * L3C * HD];
__device__ float    g_wa  [NBH * L3C * HD];
__device__ float    g_wb  [NBH * L3C * HD];
__device__ float    g_attn[5038848];
__device__ float    g_x1  [B_SZ * C_DIM * W_LEN];   // f32 residual (channel-major)
__device__ uint32_t g_xtf [B_SZ * C_DIM * W_LEN];   // tf32 bits: x, later x2
__device__ uint32_t g_x1tf[B_SZ * C_DIM * L3P];     // tf32 bits: x1 padded rows
__device__ uint32_t g_wp  [2048 * C_DIM];           // tf32 bits, k-permuted W

__device__ __forceinline__ uint32_t f2tf(float f) {
    uint32_t u; asm("cvt.rna.tf32.f32 %0, %1;" : "=r"(u) : "f"(f)); return u;
}

// ---------------------------------------------------------------------------
// Convert + merge + k-permute weights.
// Within each 32-k chunk: kp = ks*8 + (k&3)*2 + ((k>>2)&1), ks = k>>3.
// ---------------------------------------------------------------------------
__global__ void conv_w(const float* __restrict__ w0, const float* __restrict__ w1,
                       uint32_t* __restrict__ wp, int rows0, int total)
{
    int idx = blockIdx.x * 256 + threadIdx.x;
    if (idx >= total) return;
    int o = idx >> 10, kg = idx & 1023;
    int k = kg & 31, kb = kg >> 5;
    int kp = ((k >> 3) << 3) + ((k & 3) << 1) + ((k >> 2) & 1);
    const float* src = (o < rows0) ? (w0 + (size_t)o * C_DIM)
                                   : (w1 + (size_t)(o - rows0) * C_DIM);
    wp[(size_t)o * C_DIM + (kb << 5) + kp] = f2tf(src[kg]);
}

// elementwise f32 -> tf32 bits
__global__ void conv_x(const float* __restrict__ x, uint32_t* __restrict__ y, int n) {
    int i = blockIdx.x * 256 + threadIdx.x;
    if (i < n) y[i] = f2tf(x[i]);
}

// zero the padding rows of x1tf: l in [W_LEN, L3P) for every (b, c)
__global__ void pad_x1tf(uint32_t* __restrict__ y) {
    int i = blockIdx.x * 256 + threadIdx.x;           // over 4*1024*2560
    int bc = i / (L3P - W_LEN), r = i % (L3P - W_LEN);
    y[(size_t)bc * L3P + W_LEN + r] = 0u;
}

// ---------------------------------------------------------------------------
// tf32 mma.sync GEMM, operands pre-converted (u32 tf32 bits).
// 256x128x32 CTA tiles, 512 threads = 16 warps of 64x32 tiles (4x4 grid),
// 2-stage cp.async double buffering (proven R7 loop structure).
// ASTR=40: 16B-aligned cp.async AND conflict-free A-fragment LDS.64.
// MODE 0: M=2048 (qk rows<1024, v rows>=1024), scatter pos-major q/k/v.
// MODE 1: M=1024 proj, channel-major out via qbuf.
// ---------------------------------------------------------------------------
template<int MODE>
__launch_bounds__(512, 1)
__global__ void gemm_tc(const uint32_t* __restrict__ xtf, int XROW,
                        const uint32_t* __restrict__ wp,
                        const float* __restrict__ s0, const float* __restrict__ b0,
                        const float* __restrict__ s1, const float* __restrict__ b1,
                        float* __restrict__ qbuf, float* __restrict__ kbuf,
                        float* __restrict__ vbuf, int L)
{
    extern __shared__ float smf[];
    uint32_t* sm = (uint32_t*)smf;
    constexpr int ASTR = 40;    // 256 x 32 A tile, stride 40 words (160B rows)
    constexpr int BSTR = 136;   // 32 x 128 B tile, stride 136 (conflict-free)
    uint32_t* Asm[2] = { sm,         sm + 10240 };
    uint32_t* Bsm[2] = { sm + 20480, sm + 24832 };

    const int tid  = threadIdx.x;
    const int lane = tid & 31, warp = tid >> 5;
    const int wm = warp >> 2, wn = warp & 3;         // warp grid 4 x 4, tile 64x32
    const int grp = lane >> 2, qid = lane & 3;
    const int l0 = blockIdx.x * 128, o0 = blockIdx.y * 256, bz = blockIdx.z;

    const uint32_t* wmat = wp + (size_t)o0 * C_DIM;
    const bool alt = (MODE == 0) && (o0 >= 1024);
    const float* sptr = alt ? (s1 + (o0 - 1024)) : (s0 + o0);
    const float* bptr = alt ? (b1 + (o0 - 1024)) : (b0 + o0);
    const uint32_t* xbase = xtf + (size_t)bz * C_DIM * XROW;

    const int am = tid >> 3, ak = (tid & 7) * 4;   // A: rows am+64i (i<4), col ak
    const int bk = tid >> 5, bl = (tid & 31) * 4;  // B: rows bk+16i (i<2), col bl
    const int lg = l0 + bl;

    float acc[4][4][4] = {};

    auto load_tile = [&](int buf, int c0) {
        #pragma unroll
        for (int i = 0; i < 4; i++) {
            uint32_t d = (uint32_t)__cvta_generic_to_shared(&Asm[buf][(am + 64*i) * ASTR + ak]);
            const uint32_t* s = wmat + (size_t)(am + 64*i) * C_DIM + c0 + ak;
            asm volatile("cp.async.ca.shared.global [%0], [%1], 16;\n" :: "r"(d), "l"(s));
        }
        #pragma unroll
        for (int i = 0; i < 2; i++) {
            uint32_t d = (uint32_t)__cvta_generic_to_shared(&Bsm[buf][(bk + 16*i) * BSTR + bl]);
            const uint32_t* s = xbase + (size_t)(c0 + bk + 16*i) * XROW + lg;
            asm volatile("cp.async.ca.shared.global [%0], [%1], 16;\n" :: "r"(d), "l"(s));
        }
        asm volatile("cp.async.commit_group;\n");
    };

    load_tile(0, 0);
    for (int kt = 0; kt < 32; ++kt) {
        asm volatile("cp.async.wait_group 0;\n");
        __syncthreads();
        if (kt + 1 < 32) load_tile((kt + 1) & 1, (kt + 1) * 32);
        const uint32_t* Ab = Asm[kt & 1];
        const uint32_t* Bb = Bsm[kt & 1];

        #pragma unroll
        for (int ks = 0; ks < 4; ++ks) {
            uint32_t bf[4][2];
            #pragma unroll
            for (int nt = 0; nt < 4; ++nt) {
                const uint32_t* bp = Bb + (ks*8 + qid) * BSTR + wn*32 + nt*8 + grp;
                bf[nt][0] = bp[0];
                bf[nt][1] = bp[4 * BSTR];
            }
            #pragma unroll
            for (int mt = 0; mt < 4; ++mt) {
                // {a0,a2} contiguous at row*ASTR + ks*8 + qid*2
                const int base = (wm*64 + mt*16 + grp) * ASTR + ks*8 + qid*2;
                uint2 lo = *(const uint2*)&Ab[base];            // a0, a2 (row grp)
                uint2 hi = *(const uint2*)&Ab[base + 8*ASTR];   // a1, a3 (row grp+8)
                #pragma unroll
                for (int nt = 0; nt < 4; ++nt) {
                    float* d = acc[mt][nt];
                    asm volatile(
                        "mma.sync.aligned.m16n8k8.row.col.f32.tf32.tf32.f32 "
                        "{%0,%1,%2,%3},{%4,%5,%6,%7},{%8,%9},{%0,%1,%2,%3};\n"
                        : "+f"(d[0]), "+f"(d[1]), "+f"(d[2]), "+f"(d[3])
                        : "r"(lo.x), "r"(hi.x), "r"(lo.y), "r"(hi.y),
                          "r"(bf[nt][0]), "r"(bf[nt][1]));
                }
            }
        }
        __syncthreads();
    }

    // ---- epilogue via SMEM staging ----
    float* ep = smf;
    constexpr int EPS = (MODE == 0) ? 260 : 132;
    #pragma unroll
    for (int mt = 0; mt < 4; ++mt)
        #pragma unroll
        for (int nt = 0; nt < 4; ++nt) {
            int ol = wm*64 + mt*16 + grp;
            int ll = wn*32 + nt*8 + 2*qid;
            float* c = acc[mt][nt];
            if (MODE == 0) {             // ep[l][o]: 128 x 260
                ep[ll * EPS + ol]           = c[0];
                ep[(ll + 1) * EPS + ol]     = c[1];
                ep[ll * EPS + ol + 8]       = c[2];
                ep[(ll + 1) * EPS + ol + 8] = c[3];
            } else {                     // ep[o][l]: 256 x 132
                ep[ol * EPS + ll]           = c[0];
                ep[ol * EPS + ll + 1]       = c[1];
                ep[(ol + 8) * EPS + ll]     = c[2];
                ep[(ol + 8) * EPS + ll + 1] = c[3];
            }
        }
    __syncthreads();

    if (MODE == 0) {
        for (int f = tid; f < 8192; f += 512) {
            int l = f >> 6, o4 = (f & 63) << 2;
            int lgl = l0 + l;
            if (lgl >= L) continue;
            float4 v  = *(float4*)&ep[l * EPS + o4];
            float4 s4 = *(const float4*)(sptr + o4);
            float4 b4 = *(const float4*)(bptr + o4);
            float4 r = make_float4(v.x*s4.x + b4.x, v.y*s4.y + b4.y,
                                   v.z*s4.z + b4.z, v.w*s4.w + b4.w);
            int og = o0 + o4;
            float* dst;
            if (o0 < 1024) {
                int h = og >> 7, rr = (og >> 6) & 1, d0 = og & 63;
                dst = (rr ? kbuf : qbuf) + ((size_t)(bz * NHD + h) * L + lgl) * KD + d0;
            } else {
                int oc = og - 1024, h = oc >> 7, d0 = oc & 127;
                dst = vbuf + ((size_t)(bz * NHD + h) * L + lgl) * HD + d0;
            }
            *(float4*)dst = r;
        }
    } else {
        for (int f = tid; f < 8192; f += 512) {
            int o = f >> 5, l4 = (f & 31) << 2;
            float4 v = *(float4*)&ep[o * EPS + l4];
            float sc = sptr[o], bi = bptr[o];
            float4 r = make_float4(v.x*sc + bi, v.y*sc + bi, v.z*sc + bi, v.w*sc + bi);
            *(float4*)(qbuf + ((size_t)(bz * C_DIM + o0 + o)) * W_LEN + l0 + l4) = r;
        }
    }
}

// ---------------------------------------------------------------------------
// Precompute softmaxed base x base attention matrices per level.
// ---------------------------------------------------------------------------
template<int BASE, int T, int NE, bool INNER>
__launch_bounds__(256)
__global__ void attn_kernel(const float* __restrict__ q, const float* __restrict__ k,
                            float* __restrict__ attn, int L)
{
    constexpr int GT = T / BASE;
    constexpr int BB = BASE * BASE;
    __shared__ float qs[T * KD];
    __shared__ float ks[T * KD];
    __shared__ float ls[GT * BB];
    const int tile = blockIdx.x, bh = blockIdx.y, tid = threadIdx.x;

    if (INNER) {
        size_t gb = ((size_t)bh * L + (size_t)tile * T) * KD;
        const float4* q4 = (const float4*)(q + gb);
        const float4* k4 = (const float4*)(k + gb);
        for (int i = tid; i < T * KD / 4; i += 256) {
            ((float4*)qs)[i] = q4[i]; ((float4*)ks)[i] = k4[i];
        }
    } else {
        for (int i = tid; i < T * (KD/4); i += 256) {
            int p = i / (KD/4), dq = i % (KD/4);
            size_t gb = ((size_t)bh * L + (size_t)p * T + tile) * KD;
            ((float4*)qs)[i] = *((const float4*)(q + gb) + dq);
            ((float4*)ks)[i] = *((const float4*)(k + gb) + dq);
        }
    }
    __syncthreads();

    int s = 1;
    #pragma unroll
    for (int e = 0; e < NE; e++) {
        for (int it = tid; it < GT * BB; it += 256) {
            int g = it / BB, rem = it % BB;
            int J = rem / BASE, j = rem % BASE;
            int hi = g / s, lo = g % s;
            int pJ = hi * BASE * s + J * s + lo;
            int pj = hi * BASE * s + j * s + lo;
            const float4* qp = (const float4*)(qs + pj * KD);
            const float4* kp = (const float4*)(ks + pJ * KD);
            float dot = 0.f;
            #pragma unroll
            for (int dd = 0; dd < KD/4; dd++) {
                float4 a = qp[dd], b2 = kp[dd];
                dot += a.x*b2.x + a.y*b2.y + a.z*b2.z + a.w*b2.w;
            }
            ls[it] = dot * SCALE;
        }
        __syncthreads();
        const int eg = e + (INNER ? 0 : NE);
        size_t lvl = ((size_t)eg * NBH + bh) * (size_t)(L / BASE) * BB;
        for (int it = tid; it < GT * BASE; it += 256) {
            int g = it / BASE, J = it % BASE;
            const float* lg2 = ls + (g * BASE + J) * BASE;
            float m = lg2[0];
            #pragma unroll
            for (int j = 1; j < BASE; j++) m = fmaxf(m, lg2[j]);
            float ex[BASE]; float sum = 0.f;
            #pragma unroll
            for (int j = 0; j < BASE; j++) { ex[j] = __expf(lg2[j] - m); sum += ex[j]; }
            float inv = 1.f / sum;
            size_t gg = INNER ? ((size_t)tile * GT + g) : ((size_t)g * T + tile);
            float* ap = attn + lvl + gg * BB + (size_t)J * BASE;
            #pragma unroll
            for (int j = 0; j < BASE; j++) ap[j] = ex[j] * inv;
        }
        __syncthreads();
        s *= BASE;
    }
}

// ---------------------------------------------------------------------------
// Apply NE levels to v inside SMEM (one global read + write per pass).
// ---------------------------------------------------------------------------
template<int BASE, int T, int NE, bool INNER, bool ASC>
__launch_bounds__(256)
__global__ void stage_kernel(const float* __restrict__ vin, float* __restrict__ vout,
                             const float* __restrict__ attn, int L)
{
    constexpr int GT = T / BASE;
    constexpr int BB = BASE * BASE;
    __shared__ float vs[T * HD];
    __shared__ float as_[GT * BB];
    const int tile = blockIdx.x, bh = blockIdx.y, tid = threadIdx.x;

    if (INNER) {
        size_t gb = ((size_t)bh * L + (size_t)tile * T) * HD;
        const float4* v4 = (const float4*)(vin + gb);
        for (int i = tid; i < T * HD / 4; i += 256) ((float4*)vs)[i] = v4[i];
    } else {
        for (int i = tid; i < T * (HD/4); i += 256) {
            int p = i / (HD/4), dq = i % (HD/4);
            ((float4*)vs)[i] = *((const float4*)(vin + ((size_t)bh * L + (size_t)p * T + tile) * HD) + dq);
        }
    }
    __syncthreads();

    #pragma unroll
    for (int step = 0; step < NE; step++) {
        const int e = ASC ? step : (NE - 1 - step);
        int s = 1;
        #pragma unroll
        for (int t2 = 0; t2 < NE; t2++) if (t2 < e) s *= BASE;
        const int eg = e + (INNER ? 0 : NE);
        size_t lvl = ((size_t)eg * NBH + bh) * (size_t)(L / BASE) * BB;
        for (int it = tid; it < GT * BB; it += 256) {
            int g = it / BB, c = it % BB;
            size_t gg = INNER ? ((size_t)tile * GT + g) : ((size_t)g * T + tile);
            as_[it] = attn[lvl + gg * BB + c];
        }
        __syncthreads();
        for (int w = tid; w < GT * HD; w += 256) {
            int g = w >> 7, d = w & 127;
            int hi = g / s, lo = g - hi * s;
            int pb = hi * BASE * s + lo;
            float vv[BASE];
            #pragma unroll
            for (int j = 0; j < BASE; j++) vv[j] = vs[(pb + j * s) * HD + d];
            const float* ag = as_ + g * BB;
            #pragma unroll
            for (int J = 0; J < BASE; J++) {
                float o = 0.f;
                #pragma unroll
                for (int j = 0; j < BASE; j++) o += ag[J * BASE + j] * vv[j];
                vs[(pb + J * s) * HD + d] = o;
            }
        }
        __syncthreads();
    }

    if (INNER) {
        size_t gb = ((size_t)bh * L + (size_t)tile * T) * HD;
        float4* v4 = (float4*)(vout + gb);
        for (int i = tid; i < T * HD / 4; i += 256) v4[i] = ((float4*)vs)[i];
    } else {
        for (int i = tid; i < T * (HD/4); i += 256) {
            int p = i / (HD/4), dq = i % (HD/4);
            *((float4*)(vout + ((size_t)bh * L + (size_t)p * T + tile) * HD) + dq) = ((float4*)vs)[i];
        }
    }
}

// ---------------------------------------------------------------------------
// y = x + wa + wb + dwconv3(v0)*spe + bpe   (channel-major out, l < W only)
// Writes tf32 bits to ytf (row length YROW); if WF32, also writes f32 to yf.
// ---------------------------------------------------------------------------
template<bool WF32>
__launch_bounds__(256)
__global__ void combine_kernel(const float* __restrict__ xin,
                               const float* __restrict__ wa, const float* __restrict__ wb,
                               const float* __restrict__ v0,
                               const float* __restrict__ wpe, const float* __restrict__ spe,
                               const float* __restrict__ bpe,
                               float* __restrict__ yf, uint32_t* __restrict__ ytf,
                               int YROW, int L)
{
    __shared__ float s[32][129];
    __shared__ float v0s[34][129];
    const int bh = blockIdx.y;
    const int b = bh >> 3, h = bh & 7;
    const int l0 = blockIdx.x * 32;
    const int tid = threadIdx.x;

    size_t base = ((size_t)bh * L + l0) * HD;
    for (int i = tid; i < 32 * 128; i += 256) {
        int l = i >> 7, d = i & 127;
        s[l][d] = wa[base + (size_t)l * HD + d] + wb[base + (size_t)l * HD + d];
    }
    for (int i = tid; i < 34 * 128; i += 256) {
        int l = i >> 7, d = i & 127;
        int lg = l0 - 1 + l;
        float v = 0.f;
        if (lg >= 0 && lg < L) v = v0[((size_t)bh * L + lg) * HD + d];
        v0s[l][d] = v;
    }
    __syncthreads();

    const int lw = tid & 31, dw0 = tid >> 5;
    for (int dd = dw0; dd < 128; dd += 8) {
        int c = h * 128 + dd;
        float w0 = wpe[c*3+0], w1 = wpe[c*3+1], w2 = wpe[c*3+2];
        float sc = spe[c], bi = bpe[c];
        float pe = (w0 * v0s[lw][dd] + w1 * v0s[lw+1][dd] + w2 * v0s[lw+2][dd]) * sc + bi;
        size_t xi = ((size_t)b * C_DIM + c) * W_LEN + l0 + lw;
        float val = xin[xi] + s[lw][dd] + pe;
        if (WF32) yf[xi] = val;
        ytf[((size_t)b * C_DIM + c) * YROW + l0 + lw] = f2tf(val);
    }
}

// ---------------------------------------------------------------------------
extern "C" void kernel_launch(void* const* d_in, const int* in_sizes, int n_in,
                              void* d_out, int out_size)
{
    const float* x = (const float*)d_in[0];
    const float *wqk2=(const float*)d_in[1], *sqk2=(const float*)d_in[2], *bqk2=(const float*)d_in[3];
    const float *wv2 =(const float*)d_in[4], *sv2 =(const float*)d_in[5], *bv2 =(const float*)d_in[6];
    const float *wpe2=(const float*)d_in[7], *spe2=(const float*)d_in[8], *bpe2=(const float*)d_in[9];
    const float *wqk3=(const float*)d_in[10],*sqk3=(const float*)d_in[11],*bqk3=(const float*)d_in[12];
    const float *wv3 =(const float*)d_in[13],*sv3 =(const float*)d_in[14],*bv3 =(const float*)d_in[15];
    const float *wpe3=(const float*)d_in[16],*spe3=(const float*)d_in[17],*bpe3=(const float*)d_in[18];
    const float *wproj=(const float*)d_in[19],*sproj=(const float*)d_in[20],*bproj=(const float*)d_in[21];
    float* out = (float*)d_out;

    float *q, *k, *v0, *wa, *wb, *attn, *x1;
    uint32_t *xtf, *x1tf, *wp;
    cudaGetSymbolAddress((void**)&q,    g_q);
    cudaGetSymbolAddress((void**)&k,    g_k);
    cudaGetSymbolAddress((void**)&v0,   g_v0);
    cudaGetSymbolAddress((void**)&wa,   g_wa);
    cudaGetSymbolAddress((void**)&wb,   g_wb);
    cudaGetSymbolAddress((void**)&attn, g_attn);
    cudaGetSymbolAddress((void**)&x1,   g_x1);
    cudaGetSymbolAddress((void**)&xtf,  g_xtf);
    cudaGetSymbolAddress((void**)&x1tf, g_x1tf);
    cudaGetSymbolAddress((void**)&wp,   g_wp);

    const int SMEM = 135168;
    cudaFuncSetAttribute(gemm_tc<0>, cudaFuncAttributeMaxDynamicSharedMemorySize, SMEM);
    cudaFuncSetAttribute(gemm_tc<1>, cudaFuncAttributeMaxDynamicSharedMemorySize, SMEM);

    const int NX = B_SZ * C_DIM * W_LEN;
    conv_x<<<(NX + 255) / 256, 256>>>(x, xtf, NX);
    pad_x1tf<<<(B_SZ * C_DIM * (L3P - W_LEN)) / 256, 256>>>(x1tf);

    // ---- block 1: base=2, L=4096, NE=6, T=64 ----
    {
        const int L = L2C;
        conv_w<<<(2048 * 1024) / 256, 256>>>(wqk2, wv2, wp, 1024, 2048 * 1024);
        gemm_tc<0><<<dim3(32,8,4),512,SMEM>>>(xtf, W_LEN, wp, sqk2,bqk2, sv2,bv2, q,k,v0, L);
        attn_kernel<2,64,6,true ><<<dim3(64,NBH),256>>>(q,k,attn,L);
        attn_kernel<2,64,6,false><<<dim3(64,NBH),256>>>(q,k,attn,L);
        stage_kernel<2,64,6,true ,true ><<<dim3(64,NBH),256>>>(v0,wa,attn,L);
        stage_kernel<2,64,6,false,true ><<<dim3(64,NBH),256>>>(wa,wa,attn,L);
        stage_kernel<2,64,6,false,false><<<dim3(64,NBH),256>>>(v0,wb,attn,L);
        stage_kernel<2,64,6,true ,false><<<dim3(64,NBH),256>>>(wb,wb,attn,L);
        combine_kernel<true><<<dim3(128,NBH),256>>>(x, wa,wb,v0, wpe2,spe2,bpe2,
                                                    x1, x1tf, L3P, L);
    }
    // ---- block 2: base=3, L=6561, NE=4, T=81 ----
    {
        const int L = L3C;
        conv_w<<<(2048 * 1024) / 256, 256>>>(wqk3, wv3, wp, 1024, 2048 * 1024);
        gemm_tc<0><<<dim3(52,8,4),512,SMEM>>>(x1tf, L3P, wp, sqk3,bqk3, sv3,bv3, q,k,v0, L);
        attn_kernel<3,81,4,true ><<<dim3(81,NBH),256>>>(q,k,attn,L);
        attn_kernel<3,81,4,false><<<dim3(81,NBH),256>>>(q,k,attn,L);
        stage_kernel<3,81,4,true ,true ><<<dim3(81,NBH),256>>>(v0,wa,attn,L);
        stage_kernel<3,81,4,false,true ><<<dim3(81,NBH),256>>>(wa,wa,attn,L);
        stage_kernel<3,81,4,false,false><<<dim3(81,NBH),256>>>(v0,wb,attn,L);
        stage_kernel<3,81,4,true ,false><<<dim3(81,NBH),256>>>(wb,wb,attn,L);
        combine_kernel<false><<<dim3(128,NBH),256>>>(x1, wa,wb,v0, wpe3,spe3,bpe3,
                                                     nullptr, xtf, W_LEN, L);
    }
    // ---- final projection ----
    conv_w<<<(1024 * 1024) / 256, 256>>>(wproj, nullptr, wp, 1024, 1024 * 1024);
    gemm_tc<1><<<dim3(32,4,4),512,SMEM>>>(xtf, W_LEN, wp, sproj,bproj, nullptr,nullptr,
                                          out, nullptr, nullptr, W_LEN);
}

// round 11
// speedup vs baseline: 1.1156x; 1.0586x over previous
#include <cuda_runtime.h>
#include <cstdint>

#define C_DIM 1024
#define B_SZ  4
#define W_LEN 4096
#define NHD   8
#define KD    64
#define HD    128
#define L2C   4096
#define L3C   6561
#define L3P   6656
#define NBH   (B_SZ*NHD)
#define SCALE 0.125f

__device__ float    g_q   [NBH * L3C * KD];
__device__ float    g_k   [NBH * L3C * KD];
__device__ float    g_v0  [NBH * L3C * HD];
__device__ float    g_wa  [NBH * L3C * HD];
__device__ float    g_wb  [NBH * L3C * HD];
__device__ float    g_attn[5038848];
__device__ float    g_x1  [B_SZ * C_DIM * W_LEN];   // f32 residual (channel-major)
__device__ uint32_t g_xtf [B_SZ * C_DIM * W_LEN];   // tf32 bits: x, later x2
__device__ uint32_t g_x1tf[B_SZ * C_DIM * L3P];     // tf32 bits: x1 padded rows
__device__ uint32_t g_wp  [2048 * C_DIM];           // tf32 bits, k-permuted W

__device__ __forceinline__ uint32_t f2tf(float f) {
    uint32_t u; asm("cvt.rna.tf32.f32 %0, %1;" : "=r"(u) : "f"(f)); return u;
}

// ---------------------------------------------------------------------------
// Convert + merge + k-permute weights.
// Within each 32-k chunk: kp = ks*8 + (k&3)*2 + ((k>>2)&1), ks = k>>3.
// ---------------------------------------------------------------------------
__global__ void conv_w(const float* __restrict__ w0, const float* __restrict__ w1,
                       uint32_t* __restrict__ wp, int rows0, int total)
{
    int idx = blockIdx.x * 256 + threadIdx.x;
    if (idx >= total) return;
    int o = idx >> 10, kg = idx & 1023;
    int k = kg & 31, kb = kg >> 5;
    int kp = ((k >> 3) << 3) + ((k & 3) << 1) + ((k >> 2) & 1);
    const float* src = (o < rows0) ? (w0 + (size_t)o * C_DIM)
                                   : (w1 + (size_t)(o - rows0) * C_DIM);
    wp[(size_t)o * C_DIM + (kb << 5) + kp] = f2tf(src[kg]);
}

// elementwise f32 -> tf32 bits
__global__ void conv_x(const float* __restrict__ x, uint32_t* __restrict__ y, int n) {
    int i = blockIdx.x * 256 + threadIdx.x;
    if (i < n) y[i] = f2tf(x[i]);
}

// zero the padding rows of x1tf: l in [W_LEN, L3P) for every (b, c)
__global__ void pad_x1tf(uint32_t* __restrict__ y) {
    int i = blockIdx.x * 256 + threadIdx.x;           // over 4*1024*2560
    int bc = i / (L3P - W_LEN), r = i % (L3P - W_LEN);
    y[(size_t)bc * L3P + W_LEN + r] = 0u;
}

// ---------------------------------------------------------------------------
// tf32 mma.sync GEMM (R7 config: proven fastest on the legacy HMMA path).
// 256x128x32 CTA tiles, 8 warps of 64x64, 2-stage cp.async double buffering.
// ASTR=40: 16B-aligned cp.async AND conflict-free A-fragment LDS.64.
// MODE 0: M=2048 (qk rows<1024, v rows>=1024), scatter pos-major q/k/v.
// MODE 1: M=1024 proj, channel-major out via qbuf.
// ---------------------------------------------------------------------------
template<int MODE>
__launch_bounds__(256)
__global__ void gemm_tc(const uint32_t* __restrict__ xtf, int XROW,
                        const uint32_t* __restrict__ wp,
                        const float* __restrict__ s0, const float* __restrict__ b0,
                        const float* __restrict__ s1, const float* __restrict__ b1,
                        float* __restrict__ qbuf, float* __restrict__ kbuf,
                        float* __restrict__ vbuf, int L)
{
    extern __shared__ float smf[];
    uint32_t* sm = (uint32_t*)smf;
    constexpr int ASTR = 40;    // 256 x 32 A tile, stride 40 words (160B rows)
    constexpr int BSTR = 136;   // 32 x 128 B tile, stride 136 (conflict-free)
    uint32_t* Asm[2] = { sm,         sm + 10240 };
    uint32_t* Bsm[2] = { sm + 20480, sm + 24832 };

    const int tid  = threadIdx.x;
    const int lane = tid & 31, warp = tid >> 5;
    const int wm = warp >> 1, wn = warp & 1;         // warp grid 4 x 2, tile 64x64
    const int grp = lane >> 2, qid = lane & 3;
    const int l0 = blockIdx.x * 128, o0 = blockIdx.y * 256, bz = blockIdx.z;

    const uint32_t* wmat = wp + (size_t)o0 * C_DIM;
    const bool alt = (MODE == 0) && (o0 >= 1024);
    const float* sptr = alt ? (s1 + (o0 - 1024)) : (s0 + o0);
    const float* bptr = alt ? (b1 + (o0 - 1024)) : (b0 + o0);
    const uint32_t* xbase = xtf + (size_t)bz * C_DIM * XROW;

    const int am = tid >> 3, ak = (tid & 7) * 4;   // A: rows am+32i (i<8), col ak
    const int bk = tid >> 5, bl = (tid & 31) * 4;  // B: rows bk+8i (i<4), col bl
    const int lg = l0 + bl;

    float acc[4][8][4] = {};

    auto load_tile = [&](int buf, int c0) {
        #pragma unroll
        for (int i = 0; i < 8; i++) {
            uint32_t d = (uint32_t)__cvta_generic_to_shared(&Asm[buf][(am + 32*i) * ASTR + ak]);
            const uint32_t* s = wmat + (size_t)(am + 32*i) * C_DIM + c0 + ak;
            asm volatile("cp.async.ca.shared.global [%0], [%1], 16;\n" :: "r"(d), "l"(s));
        }
        #pragma unroll
        for (int i = 0; i < 4; i++) {
            uint32_t d = (uint32_t)__cvta_generic_to_shared(&Bsm[buf][(bk + 8*i) * BSTR + bl]);
            const uint32_t* s = xbase + (size_t)(c0 + bk + 8*i) * XROW + lg;
            asm volatile("cp.async.ca.shared.global [%0], [%1], 16;\n" :: "r"(d), "l"(s));
        }
        asm volatile("cp.async.commit_group;\n");
    };

    load_tile(0, 0);
    for (int kt = 0; kt < 32; ++kt) {
        asm volatile("cp.async.wait_group 0;\n");
        __syncthreads();
        if (kt + 1 < 32) load_tile((kt + 1) & 1, (kt + 1) * 32);
        const uint32_t* Ab = Asm[kt & 1];
        const uint32_t* Bb = Bsm[kt & 1];

        #pragma unroll
        for (int ks = 0; ks < 4; ++ks) {
            uint32_t bf[8][2];
            #pragma unroll
            for (int nt = 0; nt < 8; ++nt) {
                const uint32_t* bp = Bb + (ks*8 + qid) * BSTR + wn*64 + nt*8 + grp;
                bf[nt][0] = bp[0];
                bf[nt][1] = bp[4 * BSTR];
            }
            #pragma unroll
            for (int mt = 0; mt < 4; ++mt) {
                // {a0,a2} contiguous at row*ASTR + ks*8 + qid*2
                const int base = (wm*64 + mt*16 + grp) * ASTR + ks*8 + qid*2;
                uint2 lo = *(const uint2*)&Ab[base];            // a0, a2 (row grp)
                uint2 hi = *(const uint2*)&Ab[base + 8*ASTR];   // a1, a3 (row grp+8)
                #pragma unroll
                for (int nt = 0; nt < 8; ++nt) {
                    float* d = acc[mt][nt];
                    asm volatile(
                        "mma.sync.aligned.m16n8k8.row.col.f32.tf32.tf32.f32 "
                        "{%0,%1,%2,%3},{%4,%5,%6,%7},{%8,%9},{%0,%1,%2,%3};\n"
                        : "+f"(d[0]), "+f"(d[1]), "+f"(d[2]), "+f"(d[3])
                        : "r"(lo.x), "r"(hi.x), "r"(lo.y), "r"(hi.y),
                          "r"(bf[nt][0]), "r"(bf[nt][1]));
                }
            }
        }
        __syncthreads();
    }

    // ---- epilogue via SMEM staging ----
    float* ep = smf;
    constexpr int EPS = (MODE == 0) ? 260 : 132;
    #pragma unroll
    for (int mt = 0; mt < 4; ++mt)
        #pragma unroll
        for (int nt = 0; nt < 8; ++nt) {
            int ol = wm*64 + mt*16 + grp;
            int ll = wn*64 + nt*8 + 2*qid;
            float* c = acc[mt][nt];
            if (MODE == 0) {             // ep[l][o]: 128 x 260
                ep[ll * EPS + ol]           = c[0];
                ep[(ll + 1) * EPS + ol]     = c[1];
                ep[ll * EPS + ol + 8]       = c[2];
                ep[(ll + 1) * EPS + ol + 8] = c[3];
            } else {                     // ep[o][l]: 256 x 132
                ep[ol * EPS + ll]           = c[0];
                ep[ol * EPS + ll + 1]       = c[1];
                ep[(ol + 8) * EPS + ll]     = c[2];
                ep[(ol + 8) * EPS + ll + 1] = c[3];
            }
        }
    __syncthreads();

    if (MODE == 0) {
        for (int f = tid; f < 8192; f += 256) {
            int l = f >> 6, o4 = (f & 63) << 2;
            int lgl = l0 + l;
            if (lgl >= L) continue;
            float4 v  = *(float4*)&ep[l * EPS + o4];
            float4 s4 = *(const float4*)(sptr + o4);
            float4 b4 = *(const float4*)(bptr + o4);
            float4 r = make_float4(v.x*s4.x + b4.x, v.y*s4.y + b4.y,
                                   v.z*s4.z + b4.z, v.w*s4.w + b4.w);
            int og = o0 + o4;
            float* dst;
            if (o0 < 1024) {
                int h = og >> 7, rr = (og >> 6) & 1, d0 = og & 63;
                dst = (rr ? kbuf : qbuf) + ((size_t)(bz * NHD + h) * L + lgl) * KD + d0;
            } else {
                int oc = og - 1024, h = oc >> 7, d0 = oc & 127;
                dst = vbuf + ((size_t)(bz * NHD + h) * L + lgl) * HD + d0;
            }
            *(float4*)dst = r;
        }
    } else {
        for (int f = tid; f < 8192; f += 256) {
            int o = f >> 5, l4 = (f & 31) << 2;
            float4 v = *(float4*)&ep[o * EPS + l4];
            float sc = sptr[o], bi = bptr[o];
            float4 r = make_float4(v.x*sc + bi, v.y*sc + bi, v.z*sc + bi, v.w*sc + bi);
            *(float4*)(qbuf + ((size_t)(bz * C_DIM + o0 + o)) * W_LEN + l0 + l4) = r;
        }
    }
}

// ---------------------------------------------------------------------------
// Precompute softmaxed base x base attention matrices per level.
// ---------------------------------------------------------------------------
template<int BASE, int T, int NE, bool INNER>
__launch_bounds__(256)
__global__ void attn_kernel(const float* __restrict__ q, const float* __restrict__ k,
                            float* __restrict__ attn, int L)
{
    constexpr int GT = T / BASE;
    constexpr int BB = BASE * BASE;
    __shared__ float qs[T * KD];
    __shared__ float ks[T * KD];
    __shared__ float ls[GT * BB];
    const int tile = blockIdx.x, bh = blockIdx.y, tid = threadIdx.x;

    if (INNER) {
        size_t gb = ((size_t)bh * L + (size_t)tile * T) * KD;
        const float4* q4 = (const float4*)(q + gb);
        const float4* k4 = (const float4*)(k + gb);
        for (int i = tid; i < T * KD / 4; i += 256) {
            ((float4*)qs)[i] = q4[i]; ((float4*)ks)[i] = k4[i];
        }
    } else {
        for (int i = tid; i < T * (KD/4); i += 256) {
            int p = i / (KD/4), dq = i % (KD/4);
            size_t gb = ((size_t)bh * L + (size_t)p * T + tile) * KD;
            ((float4*)qs)[i] = *((const float4*)(q + gb) + dq);
            ((float4*)ks)[i] = *((const float4*)(k + gb) + dq);
        }
    }
    __syncthreads();

    int s = 1;
    #pragma unroll
    for (int e = 0; e < NE; e++) {
        for (int it = tid; it < GT * BB; it += 256) {
            int g = it / BB, rem = it % BB;
            int J = rem / BASE, j = rem % BASE;
            int hi = g / s, lo = g % s;
            int pJ = hi * BASE * s + J * s + lo;
            int pj = hi * BASE * s + j * s + lo;
            const float4* qp = (const float4*)(qs + pj * KD);
            const float4* kp = (const float4*)(ks + pJ * KD);
            float dot = 0.f;
            #pragma unroll
            for (int dd = 0; dd < KD/4; dd++) {
                float4 a = qp[dd], b2 = kp[dd];
                dot += a.x*b2.x + a.y*b2.y + a.z*b2.z + a.w*b2.w;
            }
            ls[it] = dot * SCALE;
        }
        __syncthreads();
        const int eg = e + (INNER ? 0 : NE);
        size_t lvl = ((size_t)eg * NBH + bh) * (size_t)(L / BASE) * BB;
        for (int it = tid; it < GT * BASE; it += 256) {
            int g = it / BASE, J = it % BASE;
            const float* lg2 = ls + (g * BASE + J) * BASE;
            float m = lg2[0];
            #pragma unroll
            for (int j = 1; j < BASE; j++) m = fmaxf(m, lg2[j]);
            float ex[BASE]; float sum = 0.f;
            #pragma unroll
            for (int j = 0; j < BASE; j++) { ex[j] = __expf(lg2[j] - m); sum += ex[j]; }
            float inv = 1.f / sum;
            size_t gg = INNER ? ((size_t)tile * GT + g) : ((size_t)g * T + tile);
            float* ap = attn + lvl + gg * BB + (size_t)J * BASE;
            #pragma unroll
            for (int j = 0; j < BASE; j++) ap[j] = ex[j] * inv;
        }
        __syncthreads();
        s *= BASE;
    }
}

// ---------------------------------------------------------------------------
// Apply NE levels to v inside SMEM (one global read + write per pass).
// Compute loop vectorized over pairs of d (float2): halves LDS/STS issue count.
// ---------------------------------------------------------------------------
template<int BASE, int T, int NE, bool INNER, bool ASC>
__launch_bounds__(256)
__global__ void stage_kernel(const float* __restrict__ vin, float* __restrict__ vout,
                             const float* __restrict__ attn, int L)
{
    constexpr int GT = T / BASE;
    constexpr int BB = BASE * BASE;
    constexpr int HD2 = HD / 2;
    __shared__ float vs[T * HD];
    __shared__ float as_[GT * BB];
    const int tile = blockIdx.x, bh = blockIdx.y, tid = threadIdx.x;

    if (INNER) {
        size_t gb = ((size_t)bh * L + (size_t)tile * T) * HD;
        const float4* v4 = (const float4*)(vin + gb);
        for (int i = tid; i < T * HD / 4; i += 256) ((float4*)vs)[i] = v4[i];
    } else {
        for (int i = tid; i < T * (HD/4); i += 256) {
            int p = i / (HD/4), dq = i % (HD/4);
            ((float4*)vs)[i] = *((const float4*)(vin + ((size_t)bh * L + (size_t)p * T + tile) * HD) + dq);
        }
    }
    __syncthreads();

    float2* vs2 = (float2*)vs;
    #pragma unroll
    for (int step = 0; step < NE; step++) {
        const int e = ASC ? step : (NE - 1 - step);
        int s = 1;
        #pragma unroll
        for (int t2 = 0; t2 < NE; t2++) if (t2 < e) s *= BASE;
        const int eg = e + (INNER ? 0 : NE);
        size_t lvl = ((size_t)eg * NBH + bh) * (size_t)(L / BASE) * BB;
        for (int it = tid; it < GT * BB; it += 256) {
            int g = it / BB, c = it % BB;
            size_t gg = INNER ? ((size_t)tile * GT + g) : ((size_t)g * T + tile);
            as_[it] = attn[lvl + gg * BB + c];
        }
        __syncthreads();
        for (int w = tid; w < GT * HD2; w += 256) {
            int g = w >> 6, d = w & 63;
            int hi = g / s, lo = g - hi * s;
            int pb = hi * BASE * s + lo;
            float2 vv[BASE];
            #pragma unroll
            for (int j = 0; j < BASE; j++) vv[j] = vs2[(pb + j * s) * HD2 + d];
            const float* ag = as_ + g * BB;
            #pragma unroll
            for (int J = 0; J < BASE; J++) {
                float2 o = make_float2(0.f, 0.f);
                #pragma unroll
                for (int j = 0; j < BASE; j++) {
                    float a = ag[J * BASE + j];
                    o.x += a * vv[j].x;
                    o.y += a * vv[j].y;
                }
                vs2[(pb + J * s) * HD2 + d] = o;
            }
        }
        __syncthreads();
    }

    if (INNER) {
        size_t gb = ((size_t)bh * L + (size_t)tile * T) * HD;
        float4* v4 = (float4*)(vout + gb);
        for (int i = tid; i < T * HD / 4; i += 256) v4[i] = ((float4*)vs)[i];
    } else {
        for (int i = tid; i < T * (HD/4); i += 256) {
            int p = i / (HD/4), dq = i % (HD/4);
            *((float4*)(vout + ((size_t)bh * L + (size_t)p * T + tile) * HD) + dq) = ((float4*)vs)[i];
        }
    }
}

// ---------------------------------------------------------------------------
// y = x + wa + wb + dwconv3(v0)*spe + bpe   (channel-major out, l < W only)
// Writes tf32 bits to ytf (row length YROW); if WF32, also writes f32 to yf.
// ---------------------------------------------------------------------------
template<bool WF32>
__launch_bounds__(256)
__global__ void combine_kernel(const float* __restrict__ xin,
                               const float* __restrict__ wa, const float* __restrict__ wb,
                               const float* __restrict__ v0,
                               const float* __restrict__ wpe, const float* __restrict__ spe,
                               const float* __restrict__ bpe,
                               float* __restrict__ yf, uint32_t* __restrict__ ytf,
                               int YROW, int L)
{
    __shared__ float s[32][129];
    __shared__ float v0s[34][129];
    const int bh = blockIdx.y;
    const int b = bh >> 3, h = bh & 7;
    const int l0 = blockIdx.x * 32;
    const int tid = threadIdx.x;

    size_t base = ((size_t)bh * L + l0) * HD;
    for (int i = tid; i < 32 * 128; i += 256) {
        int l = i >> 7, d = i & 127;
        s[l][d] = wa[base + (size_t)l * HD + d] + wb[base + (size_t)l * HD + d];
    }
    for (int i = tid; i < 34 * 128; i += 256) {
        int l = i >> 7, d = i & 127;
        int lg = l0 - 1 + l;
        float v = 0.f;
        if (lg >= 0 && lg < L) v = v0[((size_t)bh * L + lg) * HD + d];
        v0s[l][d] = v;
    }
    __syncthreads();

    const int lw = tid & 31, dw0 = tid >> 5;
    for (int dd = dw0; dd < 128; dd += 8) {
        int c = h * 128 + dd;
        float w0 = wpe[c*3+0], w1 = wpe[c*3+1], w2 = wpe[c*3+2];
        float sc = spe[c], bi = bpe[c];
        float pe = (w0 * v0s[lw][dd] + w1 * v0s[lw+1][dd] + w2 * v0s[lw+2][dd]) * sc + bi;
        size_t xi = ((size_t)b * C_DIM + c) * W_LEN + l0 + lw;
        float val = xin[xi] + s[lw][dd] + pe;
        if (WF32) yf[xi] = val;
        ytf[((size_t)b * C_DIM + c) * YROW + l0 + lw] = f2tf(val);
    }
}

// ---------------------------------------------------------------------------
extern "C" void kernel_launch(void* const* d_in, const int* in_sizes, int n_in,
                              void* d_out, int out_size)
{
    const float* x = (const float*)d_in[0];
    const float *wqk2=(const float*)d_in[1], *sqk2=(const float*)d_in[2], *bqk2=(const float*)d_in[3];
    const float *wv2 =(const float*)d_in[4], *sv2 =(const float*)d_in[5], *bv2 =(const float*)d_in[6];
    const float *wpe2=(const float*)d_in[7], *spe2=(const float*)d_in[8], *bpe2=(const float*)d_in[9];
    const float *wqk3=(const float*)d_in[10],*sqk3=(const float*)d_in[11],*bqk3=(const float*)d_in[12];
    const float *wv3 =(const float*)d_in[13],*sv3 =(const float*)d_in[14],*bv3 =(const float*)d_in[15];
    const float *wpe3=(const float*)d_in[16],*spe3=(const float*)d_in[17],*bpe3=(const float*)d_in[18];
    const float *wproj=(const float*)d_in[19],*sproj=(const float*)d_in[20],*bproj=(const float*)d_in[21];
    float* out = (float*)d_out;

    float *q, *k, *v0, *wa, *wb, *attn, *x1;
    uint32_t *xtf, *x1tf, *wp;
    cudaGetSymbolAddress((void**)&q,    g_q);
    cudaGetSymbolAddress((void**)&k,    g_k);
    cudaGetSymbolAddress((void**)&v0,   g_v0);
    cudaGetSymbolAddress((void**)&wa,   g_wa);
    cudaGetSymbolAddress((void**)&wb,   g_wb);
    cudaGetSymbolAddress((void**)&attn, g_attn);
    cudaGetSymbolAddress((void**)&x1,   g_x1);
    cudaGetSymbolAddress((void**)&xtf,  g_xtf);
    cudaGetSymbolAddress((void**)&x1tf, g_x1tf);
    cudaGetSymbolAddress((void**)&wp,   g_wp);

    const int SMEM = 135168;
    cudaFuncSetAttribute(gemm_tc<0>, cudaFuncAttributeMaxDynamicSharedMemorySize, SMEM);
    cudaFuncSetAttribute(gemm_tc<1>, cudaFuncAttributeMaxDynamicSharedMemorySize, SMEM);

    const int NX = B_SZ * C_DIM * W_LEN;
    conv_x<<<(NX + 255) / 256, 256>>>(x, xtf, NX);
    pad_x1tf<<<(B_SZ * C_DIM * (L3P - W_LEN)) / 256, 256>>>(x1tf);

    // ---- block 1: base=2, L=4096, NE=6, T=64 ----
    {
        const int L = L2C;
        conv_w<<<(2048 * 1024) / 256, 256>>>(wqk2, wv2, wp, 1024, 2048 * 1024);
        gemm_tc<0><<<dim3(32,8,4),256,SMEM>>>(xtf, W_LEN, wp, sqk2,bqk2, sv2,bv2, q,k,v0, L);
        attn_kernel<2,64,6,true ><<<dim3(64,NBH),256>>>(q,k,attn,L);
        attn_kernel<2,64,6,false><<<dim3(64,NBH),256>>>(q,k,attn,L);
        stage_kernel<2,64,6,true ,true ><<<dim3(64,NBH),256>>>(v0,wa,attn,L);
        stage_kernel<2,64,6,false,true ><<<dim3(64,NBH),256>>>(wa,wa,attn,L);
        stage_kernel<2,64,6,false,false><<<dim3(64,NBH),256>>>(v0,wb,attn,L);
        stage_kernel<2,64,6,true ,false><<<dim3(64,NBH),256>>>(wb,wb,attn,L);
        combine_kernel<true><<<dim3(128,NBH),256>>>(x, wa,wb,v0, wpe2,spe2,bpe2,
                                                    x1, x1tf, L3P, L);
    }
    // ---- block 2: base=3, L=6561, NE=4, T=81 ----
    {
        const int L = L3C;
        conv_w<<<(2048 * 1024) / 256, 256>>>(wqk3, wv3, wp, 1024, 2048 * 1024);
        gemm_tc<0><<<dim3(52,8,4),256,SMEM>>>(x1tf, L3P, wp, sqk3,bqk3, sv3,bv3, q,k,v0, L);
        attn_kernel<3,81,4,true ><<<dim3(81,NBH),256>>>(q,k,attn,L);
        attn_kernel<3,81,4,false><<<dim3(81,NBH),256>>>(q,k,attn,L);
        stage_kernel<3,81,4,true ,true ><<<dim3(81,NBH),256>>>(v0,wa,attn,L);
        stage_kernel<3,81,4,false,true ><<<dim3(81,NBH),256>>>(wa,wa,attn,L);
        stage_kernel<3,81,4,false,false><<<dim3(81,NBH),256>>>(v0,wb,attn,L);
        stage_kernel<3,81,4,true ,false><<<dim3(81,NBH),256>>>(wb,wb,attn,L);
        combine_kernel<false><<<dim3(128,NBH),256>>>(x1, wa,wb,v0, wpe3,spe3,bpe3,
                                                     nullptr, xtf, W_LEN, L);
    }
    // ---- final projection ----
    conv_w<<<(1024 * 1024) / 256, 256>>>(wproj, nullptr, wp, 1024, 1024 * 1024);
    gemm_tc<1><<<dim3(32,4,4),256,SMEM>>>(xtf, W_LEN, wp, sproj,bproj, nullptr,nullptr,
                                          out, nullptr, nullptr, W_LEN);
}

// round 12
// speedup vs baseline: 1.1266x; 1.0098x over previous
#include <cuda_runtime.h>
#include <cstdint>

#define C_DIM 1024
#define B_SZ  4
#define W_LEN 4096
#define NHD   8
#define KD    64
#define HD    128
#define L2C   4096
#define L3C   6561
#define L3P   6656
#define NBH   (B_SZ*NHD)
#define SCALE 0.125f

__device__ float    g_q   [NBH * L3C * KD];
__device__ float    g_k   [NBH * L3C * KD];
__device__ float    g_v0  [NBH * L3C * HD];
__device__ float    g_wa  [NBH * L3C * HD];
__device__ float    g_wb  [NBH * L3C * HD];
__device__ float    g_attn[5038848];
__device__ float    g_xf  [B_SZ * W_LEN * C_DIM];   // x position-major f32
__device__ float    g_x1  [B_SZ * W_LEN * C_DIM];   // x1 position-major f32
__device__ uint32_t g_xtf [B_SZ * W_LEN * C_DIM];   // tf32 pos-major (x, later x2)
__device__ uint32_t g_x1tf[B_SZ * L3P  * C_DIM];    // tf32 pos-major x1, padded rows
__device__ uint32_t g_wp  [2048 * C_DIM];           // tf32 bits, k-permuted W

__device__ __forceinline__ uint32_t f2tf(float f) {
    uint32_t u; asm("cvt.rna.tf32.f32 %0, %1;" : "=r"(u) : "f"(f)); return u;
}
__device__ __forceinline__ int kperm(int w) {   // w in [0,32)
    return ((w >> 3) << 3) | ((w & 3) << 1) | ((w >> 2) & 1);
}

// ---------------------------------------------------------------------------
// Convert + merge + k-permute weights (unchanged).
// ---------------------------------------------------------------------------
__global__ void conv_w(const float* __restrict__ w0, const float* __restrict__ w1,
                       uint32_t* __restrict__ wp, int rows0, int total)
{
    int idx = blockIdx.x * 256 + threadIdx.x;
    if (idx >= total) return;
    int o = idx >> 10, kg = idx & 1023;
    int k = kg & 31, kb = kg >> 5;
    const float* src = (o < rows0) ? (w0 + (size_t)o * C_DIM)
                                   : (w1 + (size_t)(o - rows0) * C_DIM);
    wp[(size_t)o * C_DIM + (kb << 5) + kperm(k)] = f2tf(src[kg]);
}

// ---------------------------------------------------------------------------
// x[b][c][l] -> pos-major: xf[b][l][c] (f32) and xtf[b][l][kperm(c)] (tf32)
// ---------------------------------------------------------------------------
__global__ void transpose_x(const float* __restrict__ x,
                            float* __restrict__ xf, uint32_t* __restrict__ xtf)
{
    __shared__ float t[32][33];
    const int b = blockIdx.z, l0 = blockIdx.x * 32, c0 = blockIdx.y * 32;
    const int tx = threadIdx.x, ty = threadIdx.y;
    #pragma unroll
    for (int j = 0; j < 4; j++)
        t[ty + 8*j][tx] = x[((size_t)b * C_DIM + c0 + ty + 8*j) * W_LEN + l0 + tx];
    __syncthreads();
    const int cp = c0 + kperm(tx);
    #pragma unroll
    for (int j = 0; j < 4; j++) {
        int l = l0 + ty + 8*j;
        float v = t[tx][ty + 8*j];
        xf [((size_t)b * W_LEN + l) * C_DIM + c0 + tx] = v;
        xtf[((size_t)b * W_LEN + l) * C_DIM + cp]      = f2tf(v);
    }
}

// zero padding rows of x1tf: l in [W_LEN, L3P), contiguous per b
__global__ void pad_x1tf(uint32_t* __restrict__ y) {
    int i = blockIdx.x * 256 + threadIdx.x;   // over 4 * 2560 * 1024
    int b = i / ((L3P - W_LEN) * C_DIM), r = i % ((L3P - W_LEN) * C_DIM);
    y[((size_t)b * L3P + W_LEN) * C_DIM + r] = 0u;
}

// ---------------------------------------------------------------------------
// tf32 mma.sync GEMM. A = wp (k-permuted), B = xtf POS-MAJOR [rows][C_DIM],
// both tiles stored at stride 40 with the k-permutation -> all fragment
// loads are LDS.64, conflict-free. 256x128x32 CTA tiles, 8 warps 64x64,
// 2-stage cp.async (R7-proven loop).
// MODE 0: M=2048 (qk<1024, v>=1024) scatter pos-major q/k/v.
// MODE 1: proj, channel-major f32 out via qbuf.
// ---------------------------------------------------------------------------
template<int MODE>
__launch_bounds__(256)
__global__ void gemm_tc(const uint32_t* __restrict__ xtf, int Lpad,
                        const uint32_t* __restrict__ wp,
                        const float* __restrict__ s0, const float* __restrict__ b0,
                        const float* __restrict__ s1, const float* __restrict__ b1,
                        float* __restrict__ qbuf, float* __restrict__ kbuf,
                        float* __restrict__ vbuf, int L)
{
    extern __shared__ float smf[];
    uint32_t* sm = (uint32_t*)smf;
    constexpr int STR = 40;     // row stride (words) for both A and B tiles
    uint32_t* Asm[2] = { sm,         sm + 10240 };
    uint32_t* Bsm[2] = { sm + 20480, sm + 25600 };

    const int tid  = threadIdx.x;
    const int lane = tid & 31, warp = tid >> 5;
    const int wm = warp >> 1, wn = warp & 1;         // 4 x 2 warps, 64x64 tiles
    const int grp = lane >> 2, qid = lane & 3;
    const int l0 = blockIdx.x * 128, o0 = blockIdx.y * 256, bz = blockIdx.z;

    const uint32_t* wmat = wp + (size_t)o0 * C_DIM;
    const bool alt = (MODE == 0) && (o0 >= 1024);
    const float* sptr = alt ? (s1 + (o0 - 1024)) : (s0 + o0);
    const float* bptr = alt ? (b1 + (o0 - 1024)) : (b0 + o0);

    const int am = tid >> 3, ak = (tid & 7) * 4;   // rows am+32i, col words ak
    const uint32_t* arow = wmat + (size_t)am * C_DIM + ak;
    const uint32_t* brow = xtf + ((size_t)bz * Lpad + l0 + am) * C_DIM + ak;

    float acc[4][8][4] = {};

    auto load_tile = [&](int buf, int c0) {
        #pragma unroll
        for (int i = 0; i < 8; i++) {
            uint32_t d = (uint32_t)__cvta_generic_to_shared(&Asm[buf][(am + 32*i) * STR + ak]);
            const uint32_t* s = arow + (size_t)(32*i) * C_DIM + c0;
            asm volatile("cp.async.ca.shared.global [%0], [%1], 16;\n" :: "r"(d), "l"(s));
        }
        #pragma unroll
        for (int i = 0; i < 4; i++) {
            uint32_t d = (uint32_t)__cvta_generic_to_shared(&Bsm[buf][(am + 32*i) * STR + ak]);
            const uint32_t* s = brow + (size_t)(32*i) * C_DIM + c0;
            asm volatile("cp.async.ca.shared.global [%0], [%1], 16;\n" :: "r"(d), "l"(s));
        }
        asm volatile("cp.async.commit_group;\n");
    };

    load_tile(0, 0);
    for (int kt = 0; kt < 32; ++kt) {
        asm volatile("cp.async.wait_group 0;\n");
        __syncthreads();
        if (kt + 1 < 32) load_tile((kt + 1) & 1, (kt + 1) * 32);
        const uint32_t* Ab = Asm[kt & 1];
        const uint32_t* Bb = Bsm[kt & 1];

        #pragma unroll
        for (int ks = 0; ks < 4; ++ks) {
            uint32_t bf[8][2];
            #pragma unroll
            for (int nt = 0; nt < 8; ++nt) {
                // pos-major B tile: {b0,b1} contiguous at n*STR + ks*8 + 2qid
                uint2 bb = *(const uint2*)&Bb[(wn*64 + nt*8 + grp) * STR + ks*8 + qid*2];
                bf[nt][0] = bb.x; bf[nt][1] = bb.y;
            }
            #pragma unroll
            for (int mt = 0; mt < 4; ++mt) {
                const int base = (wm*64 + mt*16 + grp) * STR + ks*8 + qid*2;
                uint2 lo = *(const uint2*)&Ab[base];           // a0, a2
                uint2 hi = *(const uint2*)&Ab[base + 8*STR];   // a1, a3
                #pragma unroll
                for (int nt = 0; nt < 8; ++nt) {
                    float* d = acc[mt][nt];
                    asm volatile(
                        "mma.sync.aligned.m16n8k8.row.col.f32.tf32.tf32.f32 "
                        "{%0,%1,%2,%3},{%4,%5,%6,%7},{%8,%9},{%0,%1,%2,%3};\n"
                        : "+f"(d[0]), "+f"(d[1]), "+f"(d[2]), "+f"(d[3])
                        : "r"(lo.x), "r"(hi.x), "r"(lo.y), "r"(hi.y),
                          "r"(bf[nt][0]), "r"(bf[nt][1]));
                }
            }
        }
        __syncthreads();
    }

    // ---- epilogue via SMEM staging ----
    float* ep = smf;
    constexpr int EPS = (MODE == 0) ? 260 : 132;
    #pragma unroll
    for (int mt = 0; mt < 4; ++mt)
        #pragma unroll
        for (int nt = 0; nt < 8; ++nt) {
            int ol = wm*64 + mt*16 + grp;
            int ll = wn*64 + nt*8 + 2*qid;
            float* c = acc[mt][nt];
            if (MODE == 0) {             // ep[l][o]: 128 x 260
                ep[ll * EPS + ol]           = c[0];
                ep[(ll + 1) * EPS + ol]     = c[1];
                ep[ll * EPS + ol + 8]       = c[2];
                ep[(ll + 1) * EPS + ol + 8] = c[3];
            } else {                     // ep[o][l]: 256 x 132
                ep[ol * EPS + ll]           = c[0];
                ep[ol * EPS + ll + 1]       = c[1];
                ep[(ol + 8) * EPS + ll]     = c[2];
                ep[(ol + 8) * EPS + ll + 1] = c[3];
            }
        }
    __syncthreads();

    if (MODE == 0) {
        for (int f = tid; f < 8192; f += 256) {
            int l = f >> 6, o4 = (f & 63) << 2;
            int lgl = l0 + l;
            if (lgl >= L) continue;
            float4 v  = *(float4*)&ep[l * EPS + o4];
            float4 s4 = *(const float4*)(sptr + o4);
            float4 b4 = *(const float4*)(bptr + o4);
            float4 r = make_float4(v.x*s4.x + b4.x, v.y*s4.y + b4.y,
                                   v.z*s4.z + b4.z, v.w*s4.w + b4.w);
            int og = o0 + o4;
            float* dst;
            if (o0 < 1024) {
                int h = og >> 7, rr = (og >> 6) & 1, d0 = og & 63;
                dst = (rr ? kbuf : qbuf) + ((size_t)(bz * NHD + h) * L + lgl) * KD + d0;
            } else {
                int oc = og - 1024, h = oc >> 7, d0 = oc & 127;
                dst = vbuf + ((size_t)(bz * NHD + h) * L + lgl) * HD + d0;
            }
            *(float4*)dst = r;
        }
    } else {
        for (int f = tid; f < 8192; f += 256) {
            int o = f >> 5, l4 = (f & 31) << 2;
            float4 v = *(float4*)&ep[o * EPS + l4];
            float sc = sptr[o], bi = bptr[o];
            float4 r = make_float4(v.x*sc + bi, v.y*sc + bi, v.z*sc + bi, v.w*sc + bi);
            *(float4*)(qbuf + ((size_t)(bz * C_DIM + o0 + o)) * W_LEN + l0 + l4) = r;
        }
    }
}

// ---------------------------------------------------------------------------
// Precompute softmaxed base x base attention matrices per level (unchanged).
// ---------------------------------------------------------------------------
template<int BASE, int T, int NE, bool INNER>
__launch_bounds__(256)
__global__ void attn_kernel(const float* __restrict__ q, const float* __restrict__ k,
                            float* __restrict__ attn, int L)
{
    constexpr int GT = T / BASE;
    constexpr int BB = BASE * BASE;
    __shared__ float qs[T * KD];
    __shared__ float ks[T * KD];
    __shared__ float ls[GT * BB];
    const int tile = blockIdx.x, bh = blockIdx.y, tid = threadIdx.x;

    if (INNER) {
        size_t gb = ((size_t)bh * L + (size_t)tile * T) * KD;
        const float4* q4 = (const float4*)(q + gb);
        const float4* k4 = (const float4*)(k + gb);
        for (int i = tid; i < T * KD / 4; i += 256) {
            ((float4*)qs)[i] = q4[i]; ((float4*)ks)[i] = k4[i];
        }
    } else {
        for (int i = tid; i < T * (KD/4); i += 256) {
            int p = i / (KD/4), dq = i % (KD/4);
            size_t gb = ((size_t)bh * L + (size_t)p * T + tile) * KD;
            ((float4*)qs)[i] = *((const float4*)(q + gb) + dq);
            ((float4*)ks)[i] = *((const float4*)(k + gb) + dq);
        }
    }
    __syncthreads();

    int s = 1;
    #pragma unroll
    for (int e = 0; e < NE; e++) {
        for (int it = tid; it < GT * BB; it += 256) {
            int g = it / BB, rem = it % BB;
            int J = rem / BASE, j = rem % BASE;
            int hi = g / s, lo = g % s;
            int pJ = hi * BASE * s + J * s + lo;
            int pj = hi * BASE * s + j * s + lo;
            const float4* qp = (const float4*)(qs + pj * KD);
            const float4* kp = (const float4*)(ks + pJ * KD);
            float dot = 0.f;
            #pragma unroll
            for (int dd = 0; dd < KD/4; dd++) {
                float4 a = qp[dd], b2 = kp[dd];
                dot += a.x*b2.x + a.y*b2.y + a.z*b2.z + a.w*b2.w;
            }
            ls[it] = dot * SCALE;
        }
        __syncthreads();
        const int eg = e + (INNER ? 0 : NE);
        size_t lvl = ((size_t)eg * NBH + bh) * (size_t)(L / BASE) * BB;
        for (int it = tid; it < GT * BASE; it += 256) {
            int g = it / BASE, J = it % BASE;
            const float* lg2 = ls + (g * BASE + J) * BASE;
            float m = lg2[0];
            #pragma unroll
            for (int j = 1; j < BASE; j++) m = fmaxf(m, lg2[j]);
            float ex[BASE]; float sum = 0.f;
            #pragma unroll
            for (int j = 0; j < BASE; j++) { ex[j] = __expf(lg2[j] - m); sum += ex[j]; }
            float inv = 1.f / sum;
            size_t gg = INNER ? ((size_t)tile * GT + g) : ((size_t)g * T + tile);
            float* ap = attn + lvl + gg * BB + (size_t)J * BASE;
            #pragma unroll
            for (int j = 0; j < BASE; j++) ap[j] = ex[j] * inv;
        }
        __syncthreads();
        s *= BASE;
    }
}

// ---------------------------------------------------------------------------
// Apply NE levels to v inside SMEM (float2-vectorized, unchanged from R10).
// ---------------------------------------------------------------------------
template<int BASE, int T, int NE, bool INNER, bool ASC>
__launch_bounds__(256)
__global__ void stage_kernel(const float* __restrict__ vin, float* __restrict__ vout,
                             const float* __restrict__ attn, int L)
{
    constexpr int GT = T / BASE;
    constexpr int BB = BASE * BASE;
    constexpr int HD2 = HD / 2;
    __shared__ float vs[T * HD];
    __shared__ float as_[GT * BB];
    const int tile = blockIdx.x, bh = blockIdx.y, tid = threadIdx.x;

    if (INNER) {
        size_t gb = ((size_t)bh * L + (size_t)tile * T) * HD;
        const float4* v4 = (const float4*)(vin + gb);
        for (int i = tid; i < T * HD / 4; i += 256) ((float4*)vs)[i] = v4[i];
    } else {
        for (int i = tid; i < T * (HD/4); i += 256) {
            int p = i / (HD/4), dq = i % (HD/4);
            ((float4*)vs)[i] = *((const float4*)(vin + ((size_t)bh * L + (size_t)p * T + tile) * HD) + dq);
        }
    }
    __syncthreads();

    float2* vs2 = (float2*)vs;
    #pragma unroll
    for (int step = 0; step < NE; step++) {
        const int e = ASC ? step : (NE - 1 - step);
        int s = 1;
        #pragma unroll
        for (int t2 = 0; t2 < NE; t2++) if (t2 < e) s *= BASE;
        const int eg = e + (INNER ? 0 : NE);
        size_t lvl = ((size_t)eg * NBH + bh) * (size_t)(L / BASE) * BB;
        for (int it = tid; it < GT * BB; it += 256) {
            int g = it / BB, c = it % BB;
            size_t gg = INNER ? ((size_t)tile * GT + g) : ((size_t)g * T + tile);
            as_[it] = attn[lvl + gg * BB + c];
        }
        __syncthreads();
        for (int w = tid; w < GT * HD2; w += 256) {
            int g = w >> 6, d = w & 63;
            int hi = g / s, lo = g - hi * s;
            int pb = hi * BASE * s + lo;
            float2 vv[BASE];
            #pragma unroll
            for (int j = 0; j < BASE; j++) vv[j] = vs2[(pb + j * s) * HD2 + d];
            const float* ag = as_ + g * BB;
            #pragma unroll
            for (int J = 0; J < BASE; J++) {
                float2 o = make_float2(0.f, 0.f);
                #pragma unroll
                for (int j = 0; j < BASE; j++) {
                    float a = ag[J * BASE + j];
                    o.x += a * vv[j].x;
                    o.y += a * vv[j].y;
                }
                vs2[(pb + J * s) * HD2 + d] = o;
            }
        }
        __syncthreads();
    }

    if (INNER) {
        size_t gb = ((size_t)bh * L + (size_t)tile * T) * HD;
        float4* v4 = (float4*)(vout + gb);
        for (int i = tid; i < T * HD / 4; i += 256) v4[i] = ((float4*)vs)[i];
    } else {
        for (int i = tid; i < T * (HD/4); i += 256) {
            int p = i / (HD/4), dq = i % (HD/4);
            *((float4*)(vout + ((size_t)bh * L + (size_t)p * T + tile) * HD) + dq) = ((float4*)vs)[i];
        }
    }
}

// ---------------------------------------------------------------------------
// FUSED: v2's final inner-desc stage pass + combine, all position-major.
// vin = wb (after outer-desc). Computes vs = levels_desc(vin), then
// out[l][c] = xres + vs + wa + dwconv3(v0)*spe + bpe  for gl < WV.
// Writes yf (f32 pos-major, optional) and ytf (tf32 pos-major, k-permuted).
// ---------------------------------------------------------------------------
template<int BASE, int T, int NE>
__launch_bounds__(256)
__global__ void stage_combine(const float* __restrict__ vin,
                              const float* __restrict__ wa,
                              const float* __restrict__ v0,
                              const float* __restrict__ attn,
                              const float* __restrict__ xres, int XRW,
                              const float* __restrict__ wpe, const float* __restrict__ spe,
                              const float* __restrict__ bpe,
                              float* __restrict__ yf, int YFW,
                              uint32_t* __restrict__ ytf, int YTW,
                              int L, int WV)
{
    constexpr int GT = T / BASE;
    constexpr int BB = BASE * BASE;
    constexpr int HD2 = HD / 2;
    extern __shared__ float sh[];
    float* vs  = sh;                       // T*HD
    float* v0s = sh + T * HD;              // (T+2)*HD
    float* prm = v0s + (T + 2) * HD;       // 5*128
    float* as_ = prm + 5 * 128;            // GT*BB

    const int tile = blockIdx.x, bh = blockIdx.y, tid = threadIdx.x;
    const int b = bh >> 3, h = bh & 7;

    // load wb tile (contiguous)
    {
        size_t gb = ((size_t)bh * L + (size_t)tile * T) * HD;
        const float4* v4 = (const float4*)(vin + gb);
        for (int i = tid; i < T * HD / 4; i += 256) ((float4*)vs)[i] = v4[i];
    }
    // load v0 halo tile
    for (int i = tid; i < (T + 2) * (HD/4); i += 256) {
        int l = i >> 5, dq = i & 31;
        int lg = tile * T - 1 + l;
        float4 v = (lg >= 0 && lg < L)
            ? *((const float4*)(v0 + ((size_t)bh * L + lg) * HD) + dq)
            : make_float4(0.f, 0.f, 0.f, 0.f);
        ((float4*)v0s)[l * 32 + dq] = v;
    }
    if (tid < 128) {
        int c = h * HD + tid;
        prm[tid]       = wpe[c*3];
        prm[128 + tid] = wpe[c*3+1];
        prm[256 + tid] = wpe[c*3+2];
        prm[384 + tid] = spe[c];
        prm[512 + tid] = bpe[c];
    }
    __syncthreads();

    // ---- inner-desc stage levels ----
    float2* vs2 = (float2*)vs;
    #pragma unroll
    for (int step = 0; step < NE; step++) {
        const int e = NE - 1 - step;
        int s = 1;
        #pragma unroll
        for (int t2 = 0; t2 < NE; t2++) if (t2 < e) s *= BASE;
        size_t lvl = ((size_t)e * NBH + bh) * (size_t)(L / BASE) * BB;
        for (int it = tid; it < GT * BB; it += 256) {
            int g = it / BB, c = it % BB;
            as_[it] = attn[lvl + ((size_t)tile * GT + g) * BB + c];
        }
        __syncthreads();
        for (int w = tid; w < GT * HD2; w += 256) {
            int g = w >> 6, d = w & 63;
            int hi = g / s, lo = g - hi * s;
            int pb = hi * BASE * s + lo;
            float2 vv[BASE];
            #pragma unroll
            for (int j = 0; j < BASE; j++) vv[j] = vs2[(pb + j * s) * HD2 + d];
            const float* ag = as_ + g * BB;
            #pragma unroll
            for (int J = 0; J < BASE; J++) {
                float2 o = make_float2(0.f, 0.f);
                #pragma unroll
                for (int j = 0; j < BASE; j++) {
                    float a = ag[J * BASE + j];
                    o.x += a * vv[j].x;
                    o.y += a * vv[j].y;
                }
                vs2[(pb + J * s) * HD2 + d] = o;
            }
        }
        __syncthreads();
    }

    // ---- combine: everything position-major, fully coalesced ----
    const bool wf = (yf != nullptr);
    for (int i = tid; i < T * HD; i += 256) {
        int l = i >> 7, d = i & 127;
        int gl = tile * T + l;
        if (gl >= WV) continue;
        float pe = (prm[d] * v0s[l * HD + d] + prm[128 + d] * v0s[(l + 1) * HD + d]
                  + prm[256 + d] * v0s[(l + 2) * HD + d]) * prm[384 + d] + prm[512 + d];
        int c = h * HD + d;
        float val = xres[((size_t)b * XRW + gl) * C_DIM + c]
                  + vs[l * HD + d]
                  + wa[((size_t)bh * L + gl) * HD + d]
                  + pe;
        if (wf) yf[((size_t)b * YFW + gl) * C_DIM + c] = val;
        int kb = c >> 5;
        ytf[((size_t)b * YTW + gl) * C_DIM + (kb << 5) + kperm(c & 31)] = f2tf(val);
    }
}

// ---------------------------------------------------------------------------
extern "C" void kernel_launch(void* const* d_in, const int* in_sizes, int n_in,
                              void* d_out, int out_size)
{
    const float* x = (const float*)d_in[0];
    const float *wqk2=(const float*)d_in[1], *sqk2=(const float*)d_in[2], *bqk2=(const float*)d_in[3];
    const float *wv2 =(const float*)d_in[4], *sv2 =(const float*)d_in[5], *bv2 =(const float*)d_in[6];
    const float *wpe2=(const float*)d_in[7], *spe2=(const float*)d_in[8], *bpe2=(const float*)d_in[9];
    const float *wqk3=(const float*)d_in[10],*sqk3=(const float*)d_in[11],*bqk3=(const float*)d_in[12];
    const float *wv3 =(const float*)d_in[13],*sv3 =(const float*)d_in[14],*bv3 =(const float*)d_in[15];
    const float *wpe3=(const float*)d_in[16],*spe3=(const float*)d_in[17],*bpe3=(const float*)d_in[18];
    const float *wproj=(const float*)d_in[19],*sproj=(const float*)d_in[20],*bproj=(const float*)d_in[21];
    float* out = (float*)d_out;

    float *q, *k, *v0, *wa, *wb, *attn, *x1, *xf;
    uint32_t *xtf, *x1tf, *wp;
    cudaGetSymbolAddress((void**)&q,    g_q);
    cudaGetSymbolAddress((void**)&k,    g_k);
    cudaGetSymbolAddress((void**)&v0,   g_v0);
    cudaGetSymbolAddress((void**)&wa,   g_wa);
    cudaGetSymbolAddress((void**)&wb,   g_wb);
    cudaGetSymbolAddress((void**)&attn, g_attn);
    cudaGetSymbolAddress((void**)&x1,   g_x1);
    cudaGetSymbolAddress((void**)&xf,   g_xf);
    cudaGetSymbolAddress((void**)&xtf,  g_xtf);
    cudaGetSymbolAddress((void**)&x1tf, g_x1tf);
    cudaGetSymbolAddress((void**)&wp,   g_wp);

    const int SMEM = 135168;
    cudaFuncSetAttribute(gemm_tc<0>, cudaFuncAttributeMaxDynamicSharedMemorySize, SMEM);
    cudaFuncSetAttribute(gemm_tc<1>, cudaFuncAttributeMaxDynamicSharedMemorySize, SMEM);
    const int SC2 = (64*128 + 66*128 + 5*128 + 32*4) * 4;
    const int SC3 = (81*128 + 83*128 + 5*128 + 27*9) * 4;
    cudaFuncSetAttribute(stage_combine<2,64,6>, cudaFuncAttributeMaxDynamicSharedMemorySize, SC2);
    cudaFuncSetAttribute(stage_combine<3,81,4>, cudaFuncAttributeMaxDynamicSharedMemorySize, SC3);

    transpose_x<<<dim3(128, 32, 4), dim3(32, 8)>>>(x, xf, xtf);
    pad_x1tf<<<(B_SZ * (L3P - W_LEN) * C_DIM) / 256, 256>>>(x1tf);

    // ---- block 1: base=2, L=4096, NE=6, T=64 ----
    {
        const int L = L2C;
        conv_w<<<(2048 * 1024) / 256, 256>>>(wqk2, wv2, wp, 1024, 2048 * 1024);
        gemm_tc<0><<<dim3(32,8,4),256,SMEM>>>(xtf, W_LEN, wp, sqk2,bqk2, sv2,bv2, q,k,v0, L);
        attn_kernel<2,64,6,true ><<<dim3(64,NBH),256>>>(q,k,attn,L);
        attn_kernel<2,64,6,false><<<dim3(64,NBH),256>>>(q,k,attn,L);
        stage_kernel<2,64,6,true ,true ><<<dim3(64,NBH),256>>>(v0,wa,attn,L);
        stage_kernel<2,64,6,false,true ><<<dim3(64,NBH),256>>>(wa,wa,attn,L);
        stage_kernel<2,64,6,false,false><<<dim3(64,NBH),256>>>(v0,wb,attn,L);
        stage_combine<2,64,6><<<dim3(64,NBH),256,SC2>>>(wb, wa, v0, attn,
            xf, W_LEN, wpe2,spe2,bpe2, x1, W_LEN, x1tf, L3P, L, L);
    }
    // ---- block 2: base=3, L=6561, NE=4, T=81 ----
    {
        const int L = L3C;
        conv_w<<<(2048 * 1024) / 256, 256>>>(wqk3, wv3, wp, 1024, 2048 * 1024);
        gemm_tc<0><<<dim3(52,8,4),256,SMEM>>>(x1tf, L3P, wp, sqk3,bqk3, sv3,bv3, q,k,v0, L);
        attn_kernel<3,81,4,true ><<<dim3(81,NBH),256>>>(q,k,attn,L);
        attn_kernel<3,81,4,false><<<dim3(81,NBH),256>>>(q,k,attn,L);
        stage_kernel<3,81,4,true ,true ><<<dim3(81,NBH),256>>>(v0,wa,attn,L);
        stage_kernel<3,81,4,false,true ><<<dim3(81,NBH),256>>>(wa,wa,attn,L);
        stage_kernel<3,81,4,false,false><<<dim3(81,NBH),256>>>(v0,wb,attn,L);
        stage_combine<3,81,4><<<dim3(81,NBH),256,SC3>>>(wb, wa, v0, attn,
            x1, W_LEN, wpe3,spe3,bpe3, nullptr, 0, xtf, W_LEN, L, W_LEN);
    }
    // ---- final projection ----
    conv_w<<<(1024 * 1024) / 256, 256>>>(wproj, nullptr, wp, 1024, 1024 * 1024);
    gemm_tc<1><<<dim3(32,4,4),256,SMEM>>>(xtf, W_LEN, wp, sproj,bproj, nullptr,nullptr,
                                          out, nullptr, nullptr, W_LEN);
}

// round 13
// speedup vs baseline: 1.2310x; 1.0927x over previous
#include <cuda_runtime.h>
#include <cstdint>

#define C_DIM 1024
#define B_SZ  4
#define W_LEN 4096
#define NHD   8
#define KD    64
#define HD    128
#define L2C   4096
#define L3C   6561
#define L3P   6656
#define NBH   (B_SZ*NHD)
#define SCALE 0.125f

__device__ float    g_q   [NBH * L3C * KD];
__device__ float    g_k   [NBH * L3C * KD];
__device__ float    g_v0  [NBH * L3C * HD];
__device__ float    g_wa  [NBH * L3C * HD];
__device__ float    g_wb  [NBH * L3C * HD];
__device__ float    g_attn[5038848];
__device__ float    g_xf  [B_SZ * W_LEN * C_DIM];   // x position-major f32
__device__ float    g_x1  [B_SZ * W_LEN * C_DIM];   // x1 position-major f32
__device__ uint32_t g_xtf [B_SZ * W_LEN * C_DIM];   // tf32 pos-major (x, later x2)
__device__ uint32_t g_x1tf[B_SZ * L3P  * C_DIM];    // tf32 pos-major x1 (pad rows unused)
__device__ uint32_t g_wp  [2048 * C_DIM];           // tf32 bits, k-permuted W

__device__ __forceinline__ uint32_t f2tf(float f) {
    uint32_t u; asm("cvt.rna.tf32.f32 %0, %1;" : "=r"(u) : "f"(f)); return u;
}
__device__ __forceinline__ int kperm(int w) {   // w in [0,32)
    return ((w >> 3) << 3) | ((w & 3) << 1) | ((w >> 2) & 1);
}

// ---------------------------------------------------------------------------
// Convert + merge + k-permute weights.
// ---------------------------------------------------------------------------
__global__ void conv_w(const float* __restrict__ w0, const float* __restrict__ w1,
                       uint32_t* __restrict__ wp, int rows0, int total)
{
    int idx = blockIdx.x * 256 + threadIdx.x;
    if (idx >= total) return;
    int o = idx >> 10, kg = idx & 1023;
    int k = kg & 31, kb = kg >> 5;
    const float* src = (o < rows0) ? (w0 + (size_t)o * C_DIM)
                                   : (w1 + (size_t)(o - rows0) * C_DIM);
    wp[(size_t)o * C_DIM + (kb << 5) + kperm(k)] = f2tf(src[kg]);
}

// ---------------------------------------------------------------------------
// x[b][c][l] -> pos-major: xf[b][l][c] (f32) and xtf[b][l][kperm(c)] (tf32)
// ---------------------------------------------------------------------------
__global__ void transpose_x(const float* __restrict__ x,
                            float* __restrict__ xf, uint32_t* __restrict__ xtf)
{
    __shared__ float t[32][33];
    const int b = blockIdx.z, l0 = blockIdx.x * 32, c0 = blockIdx.y * 32;
    const int tx = threadIdx.x, ty = threadIdx.y;
    #pragma unroll
    for (int j = 0; j < 4; j++)
        t[ty + 8*j][tx] = x[((size_t)b * C_DIM + c0 + ty + 8*j) * W_LEN + l0 + tx];
    __syncthreads();
    const int cp = c0 + kperm(tx);
    #pragma unroll
    for (int j = 0; j < 4; j++) {
        int l = l0 + ty + 8*j;
        float v = t[tx][ty + 8*j];
        xf [((size_t)b * W_LEN + l) * C_DIM + c0 + tx] = v;
        xtf[((size_t)b * W_LEN + l) * C_DIM + cp]      = f2tf(v);
    }
}

// ---------------------------------------------------------------------------
// tf32 mma.sync GEMM. A = wp (k-permuted), B = xtf POS-MAJOR [rows][C_DIM].
// All fragment loads LDS.64 conflict-free. 256x128x32 tiles, 8 warps 64x64.
// MODE 0: M=2048 (qk<1024, v>=1024) scatter pos-major q/k/v.
//         Tiles with l0 >= WV have zero B input -> output is exactly the
//         bias vector; skip the whole k-pipeline and scatter bias directly.
// MODE 1: proj, channel-major f32 out via qbuf.
// ---------------------------------------------------------------------------
template<int MODE>
__launch_bounds__(256)
__global__ void gemm_tc(const uint32_t* __restrict__ xtf, int Lpad,
                        const uint32_t* __restrict__ wp,
                        const float* __restrict__ s0, const float* __restrict__ b0,
                        const float* __restrict__ s1, const float* __restrict__ b1,
                        float* __restrict__ qbuf, float* __restrict__ kbuf,
                        float* __restrict__ vbuf, int L, int WV)
{
    extern __shared__ float smf[];
    uint32_t* sm = (uint32_t*)smf;
    constexpr int STR = 40;
    uint32_t* Asm[2] = { sm,         sm + 10240 };
    uint32_t* Bsm[2] = { sm + 20480, sm + 25600 };

    const int tid  = threadIdx.x;
    const int lane = tid & 31, warp = tid >> 5;
    const int wm = warp >> 1, wn = warp & 1;
    const int grp = lane >> 2, qid = lane & 3;
    const int l0 = blockIdx.x * 128, o0 = blockIdx.y * 256, bz = blockIdx.z;

    const bool alt = (MODE == 0) && (o0 >= 1024);
    const float* sptr = alt ? (s1 + (o0 - 1024)) : (s0 + o0);
    const float* bptr = alt ? (b1 + (o0 - 1024)) : (b0 + o0);

    // ---- bias fast path: zero input rows -> output == bias ----
    if (MODE == 0 && l0 >= WV) {
        for (int f = tid; f < 8192; f += 256) {
            int l = f >> 6, o4 = (f & 63) << 2;
            int lgl = l0 + l;
            if (lgl >= L) continue;
            float4 r = *(const float4*)(bptr + o4);
            int og = o0 + o4;
            float* dst;
            if (o0 < 1024) {
                int h = og >> 7, rr = (og >> 6) & 1, d0 = og & 63;
                dst = (rr ? kbuf : qbuf) + ((size_t)(bz * NHD + h) * L + lgl) * KD + d0;
            } else {
                int oc = og - 1024, h = oc >> 7, d0 = oc & 127;
                dst = vbuf + ((size_t)(bz * NHD + h) * L + lgl) * HD + d0;
            }
            *(float4*)dst = r;
        }
        return;
    }

    const uint32_t* wmat = wp + (size_t)o0 * C_DIM;
    const int am = tid >> 3, ak = (tid & 7) * 4;
    const uint32_t* arow = wmat + (size_t)am * C_DIM + ak;
    const uint32_t* brow = xtf + ((size_t)bz * Lpad + l0 + am) * C_DIM + ak;

    float acc[4][8][4] = {};

    auto load_tile = [&](int buf, int c0) {
        #pragma unroll
        for (int i = 0; i < 8; i++) {
            uint32_t d = (uint32_t)__cvta_generic_to_shared(&Asm[buf][(am + 32*i) * STR + ak]);
            const uint32_t* s = arow + (size_t)(32*i) * C_DIM + c0;
            asm volatile("cp.async.ca.shared.global [%0], [%1], 16;\n" :: "r"(d), "l"(s));
        }
        #pragma unroll
        for (int i = 0; i < 4; i++) {
            uint32_t d = (uint32_t)__cvta_generic_to_shared(&Bsm[buf][(am + 32*i) * STR + ak]);
            const uint32_t* s = brow + (size_t)(32*i) * C_DIM + c0;
            asm volatile("cp.async.ca.shared.global [%0], [%1], 16;\n" :: "r"(d), "l"(s));
        }
        asm volatile("cp.async.commit_group;\n");
    };

    load_tile(0, 0);
    for (int kt = 0; kt < 32; ++kt) {
        asm volatile("cp.async.wait_group 0;\n");
        __syncthreads();
        if (kt + 1 < 32) load_tile((kt + 1) & 1, (kt + 1) * 32);
        const uint32_t* Ab = Asm[kt & 1];
        const uint32_t* Bb = Bsm[kt & 1];

        #pragma unroll
        for (int ks = 0; ks < 4; ++ks) {
            uint32_t bf[8][2];
            #pragma unroll
            for (int nt = 0; nt < 8; ++nt) {
                uint2 bb = *(const uint2*)&Bb[(wn*64 + nt*8 + grp) * STR + ks*8 + qid*2];
                bf[nt][0] = bb.x; bf[nt][1] = bb.y;
            }
            #pragma unroll
            for (int mt = 0; mt < 4; ++mt) {
                const int base = (wm*64 + mt*16 + grp) * STR + ks*8 + qid*2;
                uint2 lo = *(const uint2*)&Ab[base];
                uint2 hi = *(const uint2*)&Ab[base + 8*STR];
                #pragma unroll
                for (int nt = 0; nt < 8; ++nt) {
                    float* d = acc[mt][nt];
                    asm volatile(
                        "mma.sync.aligned.m16n8k8.row.col.f32.tf32.tf32.f32 "
                        "{%0,%1,%2,%3},{%4,%5,%6,%7},{%8,%9},{%0,%1,%2,%3};\n"
                        : "+f"(d[0]), "+f"(d[1]), "+f"(d[2]), "+f"(d[3])
                        : "r"(lo.x), "r"(hi.x), "r"(lo.y), "r"(hi.y),
                          "r"(bf[nt][0]), "r"(bf[nt][1]));
                }
            }
        }
        __syncthreads();
    }

    // ---- epilogue via SMEM staging ----
    float* ep = smf;
    constexpr int EPS = (MODE == 0) ? 260 : 132;
    #pragma unroll
    for (int mt = 0; mt < 4; ++mt)
        #pragma unroll
        for (int nt = 0; nt < 8; ++nt) {
            int ol = wm*64 + mt*16 + grp;
            int ll = wn*64 + nt*8 + 2*qid;
            float* c = acc[mt][nt];
            if (MODE == 0) {
                ep[ll * EPS + ol]           = c[0];
                ep[(ll + 1) * EPS + ol]     = c[1];
                ep[ll * EPS + ol + 8]       = c[2];
                ep[(ll + 1) * EPS + ol + 8] = c[3];
            } else {
                ep[ol * EPS + ll]           = c[0];
                ep[ol * EPS + ll + 1]       = c[1];
                ep[(ol + 8) * EPS + ll]     = c[2];
                ep[(ol + 8) * EPS + ll + 1] = c[3];
            }
        }
    __syncthreads();

    if (MODE == 0) {
        for (int f = tid; f < 8192; f += 256) {
            int l = f >> 6, o4 = (f & 63) << 2;
            int lgl = l0 + l;
            if (lgl >= L) continue;
            float4 v  = *(float4*)&ep[l * EPS + o4];
            float4 s4 = *(const float4*)(sptr + o4);
            float4 b4 = *(const float4*)(bptr + o4);
            float4 r = make_float4(v.x*s4.x + b4.x, v.y*s4.y + b4.y,
                                   v.z*s4.z + b4.z, v.w*s4.w + b4.w);
            int og = o0 + o4;
            float* dst;
            if (o0 < 1024) {
                int h = og >> 7, rr = (og >> 6) & 1, d0 = og & 63;
                dst = (rr ? kbuf : qbuf) + ((size_t)(bz * NHD + h) * L + lgl) * KD + d0;
            } else {
                int oc = og - 1024, h = oc >> 7, d0 = oc & 127;
                dst = vbuf + ((size_t)(bz * NHD + h) * L + lgl) * HD + d0;
            }
            *(float4*)dst = r;
        }
    } else {
        for (int f = tid; f < 8192; f += 256) {
            int o = f >> 5, l4 = (f & 31) << 2;
            float4 v = *(float4*)&ep[o * EPS + l4];
            float sc = sptr[o], bi = bptr[o];
            float4 r = make_float4(v.x*sc + bi, v.y*sc + bi, v.z*sc + bi, v.w*sc + bi);
            *(float4*)(qbuf + ((size_t)(bz * C_DIM + o0 + o)) * W_LEN + l0 + l4) = r;
        }
    }
}

// ---------------------------------------------------------------------------
// Precompute softmaxed base x base attention matrices per level.
// ---------------------------------------------------------------------------
template<int BASE, int T, int NE, bool INNER>
__launch_bounds__(256)
__global__ void attn_kernel(const float* __restrict__ q, const float* __restrict__ k,
                            float* __restrict__ attn, int L)
{
    constexpr int GT = T / BASE;
    constexpr int BB = BASE * BASE;
    __shared__ float qs[T * KD];
    __shared__ float ks[T * KD];
    __shared__ float ls[GT * BB];
    const int tile = blockIdx.x, bh = blockIdx.y, tid = threadIdx.x;

    if (INNER) {
        size_t gb = ((size_t)bh * L + (size_t)tile * T) * KD;
        const float4* q4 = (const float4*)(q + gb);
        const float4* k4 = (const float4*)(k + gb);
        for (int i = tid; i < T * KD / 4; i += 256) {
            ((float4*)qs)[i] = q4[i]; ((float4*)ks)[i] = k4[i];
        }
    } else {
        for (int i = tid; i < T * (KD/4); i += 256) {
            int p = i / (KD/4), dq = i % (KD/4);
            size_t gb = ((size_t)bh * L + (size_t)p * T + tile) * KD;
            ((float4*)qs)[i] = *((const float4*)(q + gb) + dq);
            ((float4*)ks)[i] = *((const float4*)(k + gb) + dq);
        }
    }
    __syncthreads();

    int s = 1;
    #pragma unroll
    for (int e = 0; e < NE; e++) {
        for (int it = tid; it < GT * BB; it += 256) {
            int g = it / BB, rem = it % BB;
            int J = rem / BASE, j = rem % BASE;
            int hi = g / s, lo = g % s;
            int pJ = hi * BASE * s + J * s + lo;
            int pj = hi * BASE * s + j * s + lo;
            const float4* qp = (const float4*)(qs + pj * KD);
            const float4* kp = (const float4*)(ks + pJ * KD);
            float dot = 0.f;
            #pragma unroll
            for (int dd = 0; dd < KD/4; dd++) {
                float4 a = qp[dd], b2 = kp[dd];
                dot += a.x*b2.x + a.y*b2.y + a.z*b2.z + a.w*b2.w;
            }
            ls[it] = dot * SCALE;
        }
        __syncthreads();
        const int eg = e + (INNER ? 0 : NE);
        size_t lvl = ((size_t)eg * NBH + bh) * (size_t)(L / BASE) * BB;
        for (int it = tid; it < GT * BASE; it += 256) {
            int g = it / BASE, J = it % BASE;
            const float* lg2 = ls + (g * BASE + J) * BASE;
            float m = lg2[0];
            #pragma unroll
            for (int j = 1; j < BASE; j++) m = fmaxf(m, lg2[j]);
            float ex[BASE]; float sum = 0.f;
            #pragma unroll
            for (int j = 0; j < BASE; j++) { ex[j] = __expf(lg2[j] - m); sum += ex[j]; }
            float inv = 1.f / sum;
            size_t gg = INNER ? ((size_t)tile * GT + g) : ((size_t)g * T + tile);
            float* ap = attn + lvl + gg * BB + (size_t)J * BASE;
            #pragma unroll
            for (int j = 0; j < BASE; j++) ap[j] = ex[j] * inv;
        }
        __syncthreads();
        s *= BASE;
    }
}

// ---------------------------------------------------------------------------
// Apply NE levels to v inside SMEM (float2-vectorized).
// ---------------------------------------------------------------------------
template<int BASE, int T, int NE, bool INNER, bool ASC>
__launch_bounds__(256)
__global__ void stage_kernel(const float* __restrict__ vin, float* __restrict__ vout,
                             const float* __restrict__ attn, int L)
{
    constexpr int GT = T / BASE;
    constexpr int BB = BASE * BASE;
    constexpr int HD2 = HD / 2;
    __shared__ float vs[T * HD];
    __shared__ float as_[GT * BB];
    const int tile = blockIdx.x, bh = blockIdx.y, tid = threadIdx.x;

    if (INNER) {
        size_t gb = ((size_t)bh * L + (size_t)tile * T) * HD;
        const float4* v4 = (const float4*)(vin + gb);
        for (int i = tid; i < T * HD / 4; i += 256) ((float4*)vs)[i] = v4[i];
    } else {
        for (int i = tid; i < T * (HD/4); i += 256) {
            int p = i / (HD/4), dq = i % (HD/4);
            ((float4*)vs)[i] = *((const float4*)(vin + ((size_t)bh * L + (size_t)p * T + tile) * HD) + dq);
        }
    }
    __syncthreads();

    float2* vs2 = (float2*)vs;
    #pragma unroll
    for (int step = 0; step < NE; step++) {
        const int e = ASC ? step : (NE - 1 - step);
        int s = 1;
        #pragma unroll
        for (int t2 = 0; t2 < NE; t2++) if (t2 < e) s *= BASE;
        const int eg = e + (INNER ? 0 : NE);
        size_t lvl = ((size_t)eg * NBH + bh) * (size_t)(L / BASE) * BB;
        for (int it = tid; it < GT * BB; it += 256) {
            int g = it / BB, c = it % BB;
            size_t gg = INNER ? ((size_t)tile * GT + g) : ((size_t)g * T + tile);
            as_[it] = attn[lvl + gg * BB + c];
        }
        __syncthreads();
        for (int w = tid; w < GT * HD2; w += 256) {
            int g = w >> 6, d = w & 63;
            int hi = g / s, lo = g - hi * s;
            int pb = hi * BASE * s + lo;
            float2 vv[BASE];
            #pragma unroll
            for (int j = 0; j < BASE; j++) vv[j] = vs2[(pb + j * s) * HD2 + d];
            const float* ag = as_ + g * BB;
            #pragma unroll
            for (int J = 0; J < BASE; J++) {
                float2 o = make_float2(0.f, 0.f);
                #pragma unroll
                for (int j = 0; j < BASE; j++) {
                    float a = ag[J * BASE + j];
                    o.x += a * vv[j].x;
                    o.y += a * vv[j].y;
                }
                vs2[(pb + J * s) * HD2 + d] = o;
            }
        }
        __syncthreads();
    }

    if (INNER) {
        size_t gb = ((size_t)bh * L + (size_t)tile * T) * HD;
        float4* v4 = (float4*)(vout + gb);
        for (int i = tid; i < T * HD / 4; i += 256) v4[i] = ((float4*)vs)[i];
    } else {
        for (int i = tid; i < T * (HD/4); i += 256) {
            int p = i / (HD/4), dq = i % (HD/4);
            *((float4*)(vout + ((size_t)bh * L + (size_t)p * T + tile) * HD) + dq) = ((float4*)vs)[i];
        }
    }
}

// ---------------------------------------------------------------------------
// FUSED: v2's final inner-desc stage pass + combine, all position-major.
// ---------------------------------------------------------------------------
template<int BASE, int T, int NE>
__launch_bounds__(256)
__global__ void stage_combine(const float* __restrict__ vin,
                              const float* __restrict__ wa,
                              const float* __restrict__ v0,
                              const float* __restrict__ attn,
                              const float* __restrict__ xres, int XRW,
                              const float* __restrict__ wpe, const float* __restrict__ spe,
                              const float* __restrict__ bpe,
                              float* __restrict__ yf, int YFW,
                              uint32_t* __restrict__ ytf, int YTW,
                              int L, int WV)
{
    constexpr int GT = T / BASE;
    constexpr int BB = BASE * BASE;
    constexpr int HD2 = HD / 2;
    extern __shared__ float sh[];
    float* vs  = sh;
    float* v0s = sh + T * HD;
    float* prm = v0s + (T + 2) * HD;
    float* as_ = prm + 5 * 128;

    const int tile = blockIdx.x, bh = blockIdx.y, tid = threadIdx.x;
    const int b = bh >> 3, h = bh & 7;

    {
        size_t gb = ((size_t)bh * L + (size_t)tile * T) * HD;
        const float4* v4 = (const float4*)(vin + gb);
        for (int i = tid; i < T * HD / 4; i += 256) ((float4*)vs)[i] = v4[i];
    }
    for (int i = tid; i < (T + 2) * (HD/4); i += 256) {
        int l = i >> 5, dq = i & 31;
        int lg = tile * T - 1 + l;
        float4 v = (lg >= 0 && lg < L)
            ? *((const float4*)(v0 + ((size_t)bh * L + lg) * HD) + dq)
            : make_float4(0.f, 0.f, 0.f, 0.f);
        ((float4*)v0s)[l * 32 + dq] = v;
    }
    if (tid < 128) {
        int c = h * HD + tid;
        prm[tid]       = wpe[c*3];
        prm[128 + tid] = wpe[c*3+1];
        prm[256 + tid] = wpe[c*3+2];
        prm[384 + tid] = spe[c];
        prm[512 + tid] = bpe[c];
    }
    __syncthreads();

    float2* vs2 = (float2*)vs;
    #pragma unroll
    for (int step = 0; step < NE; step++) {
        const int e = NE - 1 - step;
        int s = 1;
        #pragma unroll
        for (int t2 = 0; t2 < NE; t2++) if (t2 < e) s *= BASE;
        size_t lvl = ((size_t)e * NBH + bh) * (size_t)(L / BASE) * BB;
        for (int it = tid; it < GT * BB; it += 256) {
            int g = it / BB, c = it % BB;
            as_[it] = attn[lvl + ((size_t)tile * GT + g) * BB + c];
        }
        __syncthreads();
        for (int w = tid; w < GT * HD2; w += 256) {
            int g = w >> 6, d = w & 63;
            int hi = g / s, lo = g - hi * s;
            int pb = hi * BASE * s + lo;
            float2 vv[BASE];
            #pragma unroll
            for (int j = 0; j < BASE; j++) vv[j] = vs2[(pb + j * s) * HD2 + d];
            const float* ag = as_ + g * BB;
            #pragma unroll
            for (int J = 0; J < BASE; J++) {
                float2 o = make_float2(0.f, 0.f);
                #pragma unroll
                for (int j = 0; j < BASE; j++) {
                    float a = ag[J * BASE + j];
                    o.x += a * vv[j].x;
                    o.y += a * vv[j].y;
                }
                vs2[(pb + J * s) * HD2 + d] = o;
            }
        }
        __syncthreads();
    }

    const bool wf = (yf != nullptr);
    for (int i = tid; i < T * HD; i += 256) {
        int l = i >> 7, d = i & 127;
        int gl = tile * T + l;
        if (gl >= WV) continue;
        float pe = (prm[d] * v0s[l * HD + d] + prm[128 + d] * v0s[(l + 1) * HD + d]
                  + prm[256 + d] * v0s[(l + 2) * HD + d]) * prm[384 + d] + prm[512 + d];
        int c = h * HD + d;
        float val = xres[((size_t)b * XRW + gl) * C_DIM + c]
                  + vs[l * HD + d]
                  + wa[((size_t)bh * L + gl) * HD + d]
                  + pe;
        if (wf) yf[((size_t)b * YFW + gl) * C_DIM + c] = val;
        int kb = c >> 5;
        ytf[((size_t)b * YTW + gl) * C_DIM + (kb << 5) + kperm(c & 31)] = f2tf(val);
    }
}

// ---------------------------------------------------------------------------
extern "C" void kernel_launch(void* const* d_in, const int* in_sizes, int n_in,
                              void* d_out, int out_size)
{
    const float* x = (const float*)d_in[0];
    const float *wqk2=(const float*)d_in[1], *sqk2=(const float*)d_in[2], *bqk2=(const float*)d_in[3];
    const float *wv2 =(const float*)d_in[4], *sv2 =(const float*)d_in[5], *bv2 =(const float*)d_in[6];
    const float *wpe2=(const float*)d_in[7], *spe2=(const float*)d_in[8], *bpe2=(const float*)d_in[9];
    const float *wqk3=(const float*)d_in[10],*sqk3=(const float*)d_in[11],*bqk3=(const float*)d_in[12];
    const float *wv3 =(const float*)d_in[13],*sv3 =(const float*)d_in[14],*bv3 =(const float*)d_in[15];
    const float *wpe3=(const float*)d_in[16],*spe3=(const float*)d_in[17],*bpe3=(const float*)d_in[18];
    const float *wproj=(const float*)d_in[19],*sproj=(const float*)d_in[20],*bproj=(const float*)d_in[21];
    float* out = (float*)d_out;

    float *q, *k, *v0, *wa, *wb, *attn, *x1, *xf;
    uint32_t *xtf, *x1tf, *wp;
    cudaGetSymbolAddress((void**)&q,    g_q);
    cudaGetSymbolAddress((void**)&k,    g_k);
    cudaGetSymbolAddress((void**)&v0,   g_v0);
    cudaGetSymbolAddress((void**)&wa,   g_wa);
    cudaGetSymbolAddress((void**)&wb,   g_wb);
    cudaGetSymbolAddress((void**)&attn, g_attn);
    cudaGetSymbolAddress((void**)&x1,   g_x1);
    cudaGetSymbolAddress((void**)&xf,   g_xf);
    cudaGetSymbolAddress((void**)&xtf,  g_xtf);
    cudaGetSymbolAddress((void**)&x1tf, g_x1tf);
    cudaGetSymbolAddress((void**)&wp,   g_wp);

    const int SMEM = 135168;
    cudaFuncSetAttribute(gemm_tc<0>, cudaFuncAttributeMaxDynamicSharedMemorySize, SMEM);
    cudaFuncSetAttribute(gemm_tc<1>, cudaFuncAttributeMaxDynamicSharedMemorySize, SMEM);
    const int SC2 = (64*128 + 66*128 + 5*128 + 32*4) * 4;
    const int SC3 = (81*128 + 83*128 + 5*128 + 27*9) * 4;
    cudaFuncSetAttribute(stage_combine<2,64,6>, cudaFuncAttributeMaxDynamicSharedMemorySize, SC2);
    cudaFuncSetAttribute(stage_combine<3,81,4>, cudaFuncAttributeMaxDynamicSharedMemorySize, SC3);

    transpose_x<<<dim3(128, 32, 4), dim3(32, 8)>>>(x, xf, xtf);

    // ---- block 1: base=2, L=4096, NE=6, T=64 ----
    {
        const int L = L2C;
        conv_w<<<(2048 * 1024) / 256, 256>>>(wqk2, wv2, wp, 1024, 2048 * 1024);
        gemm_tc<0><<<dim3(32,8,4),256,SMEM>>>(xtf, W_LEN, wp, sqk2,bqk2, sv2,bv2, q,k,v0, L, W_LEN);
        attn_kernel<2,64,6,true ><<<dim3(64,NBH),256>>>(q,k,attn,L);
        attn_kernel<2,64,6,false><<<dim3(64,NBH),256>>>(q,k,attn,L);
        stage_kernel<2,64,6,true ,true ><<<dim3(64,NBH),256>>>(v0,wa,attn,L);
        stage_kernel<2,64,6,false,true ><<<dim3(64,NBH),256>>>(wa,wa,attn,L);
        stage_kernel<2,64,6,false,false><<<dim3(64,NBH),256>>>(v0,wb,attn,L);
        stage_combine<2,64,6><<<dim3(64,NBH),256,SC2>>>(wb, wa, v0, attn,
            xf, W_LEN, wpe2,spe2,bpe2, x1, W_LEN, x1tf, L3P, L, L);
    }
    // ---- block 2: base=3, L=6561, NE=4, T=81 ----
    {
        const int L = L3C;
        conv_w<<<(2048 * 1024) / 256, 256>>>(wqk3, wv3, wp, 1024, 2048 * 1024);
        gemm_tc<0><<<dim3(52,8,4),256,SMEM>>>(x1tf, L3P, wp, sqk3,bqk3, sv3,bv3, q,k,v0, L, W_LEN);
        attn_kernel<3,81,4,true ><<<dim3(81,NBH),256>>>(q,k,attn,L);
        attn_kernel<3,81,4,false><<<dim3(81,NBH),256>>>(q,k,attn,L);
        stage_kernel<3,81,4,true ,true ><<<dim3(81,NBH),256>>>(v0,wa,attn,L);
        stage_kernel<3,81,4,false,true ><<<dim3(81,NBH),256>>>(wa,wa,attn,L);
        stage_kernel<3,81,4,false,false><<<dim3(81,NBH),256>>>(v0,wb,attn,L);
        stage_combine<3,81,4><<<dim3(81,NBH),256,SC3>>>(wb, wa, v0, attn,
            x1, W_LEN, wpe3,spe3,bpe3, nullptr, 0, xtf, W_LEN, L, W_LEN);
    }
    // ---- final projection ----
    conv_w<<<(1024 * 1024) / 256, 256>>>(wproj, nullptr, wp, 1024, 1024 * 1024);
    gemm_tc<1><<<dim3(32,4,4),256,SMEM>>>(xtf, W_LEN, wp, sproj,bproj, nullptr,nullptr,
                                          out, nullptr, nullptr, W_LEN, W_LEN);
}

// round 14
// speedup vs baseline: 1.4230x; 1.1560x over previous
#include <cuda_runtime.h>
#include <cstdint>

#define C_DIM 1024
#define B_SZ  4
#define W_LEN 4096
#define NHD   8
#define KD    64
#define HD    128
#define L2C   4096
#define L3C   6561
#define L3P   6656
#define NBH   (B_SZ*NHD)
#define SCALE 0.125f

__device__ float    g_q   [NBH * L3C * KD];
__device__ float    g_k   [NBH * L3C * KD];
__device__ float    g_v0  [NBH * L3C * HD];
__device__ float    g_wa  [NBH * L3C * HD];
__device__ float    g_wb  [NBH * L3C * HD];
__device__ float    g_attn[5038848];
__device__ float    g_xf  [B_SZ * W_LEN * C_DIM];   // x position-major f32
__device__ float    g_x1  [B_SZ * W_LEN * C_DIM];   // x1 position-major f32
__device__ uint32_t g_xtf [B_SZ * W_LEN * C_DIM];   // tf32 pos-major (x, later x2)
__device__ uint32_t g_x1tf[B_SZ * L3P  * C_DIM];    // tf32 pos-major x1 (pad rows unused)
__device__ uint32_t g_wp  [2048 * C_DIM];           // tf32 bits, k-permuted W

__device__ __forceinline__ uint32_t f2tf(float f) {
    uint32_t u; asm("cvt.rna.tf32.f32 %0, %1;" : "=r"(u) : "f"(f)); return u;
}
__device__ __forceinline__ int kperm(int w) {   // w in [0,32)
    return ((w >> 3) << 3) | ((w & 3) << 1) | ((w >> 2) & 1);
}

// ---------------------------------------------------------------------------
// Convert + merge + k-permute weights.
// ---------------------------------------------------------------------------
__global__ void conv_w(const float* __restrict__ w0, const float* __restrict__ w1,
                       uint32_t* __restrict__ wp, int rows0, int total)
{
    int idx = blockIdx.x * 256 + threadIdx.x;
    if (idx >= total) return;
    int o = idx >> 10, kg = idx & 1023;
    int k = kg & 31, kb = kg >> 5;
    const float* src = (o < rows0) ? (w0 + (size_t)o * C_DIM)
                                   : (w1 + (size_t)(o - rows0) * C_DIM);
    wp[(size_t)o * C_DIM + (kb << 5) + kperm(k)] = f2tf(src[kg]);
}

// ---------------------------------------------------------------------------
// x[b][c][l] -> pos-major: xf[b][l][c] (f32) and xtf[b][l][kperm(c)] (tf32)
// ---------------------------------------------------------------------------
__global__ void transpose_x(const float* __restrict__ x,
                            float* __restrict__ xf, uint32_t* __restrict__ xtf)
{
    __shared__ float t[32][33];
    const int b = blockIdx.z, l0 = blockIdx.x * 32, c0 = blockIdx.y * 32;
    const int tx = threadIdx.x, ty = threadIdx.y;
    #pragma unroll
    for (int j = 0; j < 4; j++)
        t[ty + 8*j][tx] = x[((size_t)b * C_DIM + c0 + ty + 8*j) * W_LEN + l0 + tx];
    __syncthreads();
    const int cp = c0 + kperm(tx);
    #pragma unroll
    for (int j = 0; j < 4; j++) {
        int l = l0 + ty + 8*j;
        float v = t[tx][ty + 8*j];
        xf [((size_t)b * W_LEN + l) * C_DIM + c0 + tx] = v;
        xtf[((size_t)b * W_LEN + l) * C_DIM + cp]      = f2tf(v);
    }
}

// ---------------------------------------------------------------------------
// tf32 mma.sync GEMM (unchanged from R12).
// ---------------------------------------------------------------------------
template<int MODE>
__launch_bounds__(256)
__global__ void gemm_tc(const uint32_t* __restrict__ xtf, int Lpad,
                        const uint32_t* __restrict__ wp,
                        const float* __restrict__ s0, const float* __restrict__ b0,
                        const float* __restrict__ s1, const float* __restrict__ b1,
                        float* __restrict__ qbuf, float* __restrict__ kbuf,
                        float* __restrict__ vbuf, int L, int WV)
{
    extern __shared__ float smf[];
    uint32_t* sm = (uint32_t*)smf;
    constexpr int STR = 40;
    uint32_t* Asm[2] = { sm,         sm + 10240 };
    uint32_t* Bsm[2] = { sm + 20480, sm + 25600 };

    const int tid  = threadIdx.x;
    const int lane = tid & 31, warp = tid >> 5;
    const int wm = warp >> 1, wn = warp & 1;
    const int grp = lane >> 2, qid = lane & 3;
    const int l0 = blockIdx.x * 128, o0 = blockIdx.y * 256, bz = blockIdx.z;

    const bool alt = (MODE == 0) && (o0 >= 1024);
    const float* sptr = alt ? (s1 + (o0 - 1024)) : (s0 + o0);
    const float* bptr = alt ? (b1 + (o0 - 1024)) : (b0 + o0);

    if (MODE == 0 && l0 >= WV) {
        for (int f = tid; f < 8192; f += 256) {
            int l = f >> 6, o4 = (f & 63) << 2;
            int lgl = l0 + l;
            if (lgl >= L) continue;
            float4 r = *(const float4*)(bptr + o4);
            int og = o0 + o4;
            float* dst;
            if (o0 < 1024) {
                int h = og >> 7, rr = (og >> 6) & 1, d0 = og & 63;
                dst = (rr ? kbuf : qbuf) + ((size_t)(bz * NHD + h) * L + lgl) * KD + d0;
            } else {
                int oc = og - 1024, h = oc >> 7, d0 = oc & 127;
                dst = vbuf + ((size_t)(bz * NHD + h) * L + lgl) * HD + d0;
            }
            *(float4*)dst = r;
        }
        return;
    }

    const uint32_t* wmat = wp + (size_t)o0 * C_DIM;
    const int am = tid >> 3, ak = (tid & 7) * 4;
    const uint32_t* arow = wmat + (size_t)am * C_DIM + ak;
    const uint32_t* brow = xtf + ((size_t)bz * Lpad + l0 + am) * C_DIM + ak;

    float acc[4][8][4] = {};

    auto load_tile = [&](int buf, int c0) {
        #pragma unroll
        for (int i = 0; i < 8; i++) {
            uint32_t d = (uint32_t)__cvta_generic_to_shared(&Asm[buf][(am + 32*i) * STR + ak]);
            const uint32_t* s = arow + (size_t)(32*i) * C_DIM + c0;
            asm volatile("cp.async.ca.shared.global [%0], [%1], 16;\n" :: "r"(d), "l"(s));
        }
        #pragma unroll
        for (int i = 0; i < 4; i++) {
            uint32_t d = (uint32_t)__cvta_generic_to_shared(&Bsm[buf][(am + 32*i) * STR + ak]);
            const uint32_t* s = brow + (size_t)(32*i) * C_DIM + c0;
            asm volatile("cp.async.ca.shared.global [%0], [%1], 16;\n" :: "r"(d), "l"(s));
        }
        asm volatile("cp.async.commit_group;\n");
    };

    load_tile(0, 0);
    for (int kt = 0; kt < 32; ++kt) {
        asm volatile("cp.async.wait_group 0;\n");
        __syncthreads();
        if (kt + 1 < 32) load_tile((kt + 1) & 1, (kt + 1) * 32);
        const uint32_t* Ab = Asm[kt & 1];
        const uint32_t* Bb = Bsm[kt & 1];

        #pragma unroll
        for (int ks = 0; ks < 4; ++ks) {
            uint32_t bf[8][2];
            #pragma unroll
            for (int nt = 0; nt < 8; ++nt) {
                uint2 bb = *(const uint2*)&Bb[(wn*64 + nt*8 + grp) * STR + ks*8 + qid*2];
                bf[nt][0] = bb.x; bf[nt][1] = bb.y;
            }
            #pragma unroll
            for (int mt = 0; mt < 4; ++mt) {
                const int base = (wm*64 + mt*16 + grp) * STR + ks*8 + qid*2;
                uint2 lo = *(const uint2*)&Ab[base];
                uint2 hi = *(const uint2*)&Ab[base + 8*STR];
                #pragma unroll
                for (int nt = 0; nt < 8; ++nt) {
                    float* d = acc[mt][nt];
                    asm volatile(
                        "mma.sync.aligned.m16n8k8.row.col.f32.tf32.tf32.f32 "
                        "{%0,%1,%2,%3},{%4,%5,%6,%7},{%8,%9},{%0,%1,%2,%3};\n"
                        : "+f"(d[0]), "+f"(d[1]), "+f"(d[2]), "+f"(d[3])
                        : "r"(lo.x), "r"(hi.x), "r"(lo.y), "r"(hi.y),
                          "r"(bf[nt][0]), "r"(bf[nt][1]));
                }
            }
        }
        __syncthreads();
    }

    float* ep = smf;
    constexpr int EPS = (MODE == 0) ? 260 : 132;
    #pragma unroll
    for (int mt = 0; mt < 4; ++mt)
        #pragma unroll
        for (int nt = 0; nt < 8; ++nt) {
            int ol = wm*64 + mt*16 + grp;
            int ll = wn*64 + nt*8 + 2*qid;
            float* c = acc[mt][nt];
            if (MODE == 0) {
                ep[ll * EPS + ol]           = c[0];
                ep[(ll + 1) * EPS + ol]     = c[1];
                ep[ll * EPS + ol + 8]       = c[2];
                ep[(ll + 1) * EPS + ol + 8] = c[3];
            } else {
                ep[ol * EPS + ll]           = c[0];
                ep[ol * EPS + ll + 1]       = c[1];
                ep[(ol + 8) * EPS + ll]     = c[2];
                ep[(ol + 8) * EPS + ll + 1] = c[3];
            }
        }
    __syncthreads();

    if (MODE == 0) {
        for (int f = tid; f < 8192; f += 256) {
            int l = f >> 6, o4 = (f & 63) << 2;
            int lgl = l0 + l;
            if (lgl >= L) continue;
            float4 v  = *(float4*)&ep[l * EPS + o4];
            float4 s4 = *(const float4*)(sptr + o4);
            float4 b4 = *(const float4*)(bptr + o4);
            float4 r = make_float4(v.x*s4.x + b4.x, v.y*s4.y + b4.y,
                                   v.z*s4.z + b4.z, v.w*s4.w + b4.w);
            int og = o0 + o4;
            float* dst;
            if (o0 < 1024) {
                int h = og >> 7, rr = (og >> 6) & 1, d0 = og & 63;
                dst = (rr ? kbuf : qbuf) + ((size_t)(bz * NHD + h) * L + lgl) * KD + d0;
            } else {
                int oc = og - 1024, h = oc >> 7, d0 = oc & 127;
                dst = vbuf + ((size_t)(bz * NHD + h) * L + lgl) * HD + d0;
            }
            *(float4*)dst = r;
        }
    } else {
        for (int f = tid; f < 8192; f += 256) {
            int o = f >> 5, l4 = (f & 31) << 2;
            float4 v = *(float4*)&ep[o * EPS + l4];
            float sc = sptr[o], bi = bptr[o];
            float4 r = make_float4(v.x*sc + bi, v.y*sc + bi, v.z*sc + bi, v.w*sc + bi);
            *(float4*)(qbuf + ((size_t)(bz * C_DIM + o0 + o)) * W_LEN + l0 + l4) = r;
        }
    }
}

// ---------------------------------------------------------------------------
// Attention matrices. q/k smem rows padded to stride 68 (KD+4): row start
// bank = 4*pj mod 32 -> the 8 distinct rows per half-warp phase hit distinct
// bank groups -> conflict-free fragment loads (was 16-way at stride 64).
// ---------------------------------------------------------------------------
template<int BASE, int T, int NE, bool INNER>
__launch_bounds__(256)
__global__ void attn_kernel(const float* __restrict__ q, const float* __restrict__ k,
                            float* __restrict__ attn, int L)
{
    constexpr int GT = T / BASE;
    constexpr int BB = BASE * BASE;
    constexpr int QSTR = KD + 4;    // 68 floats, 272B (16B-aligned rows)
    __shared__ float qs[T * QSTR];
    __shared__ float ks[T * QSTR];
    __shared__ float ls[GT * BB];
    const int tile = blockIdx.x, bh = blockIdx.y, tid = threadIdx.x;

    for (int i = tid; i < T * (KD/4); i += 256) {
        int p = i >> 4, dq = i & 15;
        size_t gb;
        if (INNER) gb = ((size_t)bh * L + (size_t)tile * T + p) * KD;
        else       gb = ((size_t)bh * L + (size_t)p * T + tile) * KD;
        *(float4*)(qs + p * QSTR + dq * 4) = *((const float4*)(q + gb) + dq);
        *(float4*)(ks + p * QSTR + dq * 4) = *((const float4*)(k + gb) + dq);
    }
    __syncthreads();

    int s = 1;
    #pragma unroll
    for (int e = 0; e < NE; e++) {
        for (int it = tid; it < GT * BB; it += 256) {
            int g = it / BB, rem = it % BB;
            int J = rem / BASE, j = rem % BASE;
            int hi = g / s, lo = g % s;
            int pJ = hi * BASE * s + J * s + lo;
            int pj = hi * BASE * s + j * s + lo;
            const float4* qp = (const float4*)(qs + pj * QSTR);
            const float4* kp = (const float4*)(ks + pJ * QSTR);
            float dot = 0.f;
            #pragma unroll
            for (int dd = 0; dd < KD/4; dd++) {
                float4 a = qp[dd], b2 = kp[dd];
                dot += a.x*b2.x + a.y*b2.y + a.z*b2.z + a.w*b2.w;
            }
            ls[it] = dot * SCALE;
        }
        __syncthreads();
        const int eg = e + (INNER ? 0 : NE);
        size_t lvl = ((size_t)eg * NBH + bh) * (size_t)(L / BASE) * BB;
        for (int it = tid; it < GT * BASE; it += 256) {
            int g = it / BASE, J = it % BASE;
            const float* lg2 = ls + (g * BASE + J) * BASE;
            float m = lg2[0];
            #pragma unroll
            for (int j = 1; j < BASE; j++) m = fmaxf(m, lg2[j]);
            float ex[BASE]; float sum = 0.f;
            #pragma unroll
            for (int j = 0; j < BASE; j++) { ex[j] = __expf(lg2[j] - m); sum += ex[j]; }
            float inv = 1.f / sum;
            size_t gg = INNER ? ((size_t)tile * GT + g) : ((size_t)g * T + tile);
            float* ap = attn + lvl + gg * BB + (size_t)J * BASE;
            #pragma unroll
            for (int j = 0; j < BASE; j++) ap[j] = ex[j] * inv;
        }
        __syncthreads();
        s *= BASE;
    }
}

// ---------------------------------------------------------------------------
// Apply NE levels to v inside SMEM (float2-vectorized).
// ---------------------------------------------------------------------------
template<int BASE, int T, int NE, bool INNER, bool ASC>
__launch_bounds__(256)
__global__ void stage_kernel(const float* __restrict__ vin, float* __restrict__ vout,
                             const float* __restrict__ attn, int L)
{
    constexpr int GT = T / BASE;
    constexpr int BB = BASE * BASE;
    constexpr int HD2 = HD / 2;
    __shared__ float vs[T * HD];
    __shared__ float as_[GT * BB];
    const int tile = blockIdx.x, bh = blockIdx.y, tid = threadIdx.x;

    if (INNER) {
        size_t gb = ((size_t)bh * L + (size_t)tile * T) * HD;
        const float4* v4 = (const float4*)(vin + gb);
        for (int i = tid; i < T * HD / 4; i += 256) ((float4*)vs)[i] = v4[i];
    } else {
        for (int i = tid; i < T * (HD/4); i += 256) {
            int p = i / (HD/4), dq = i % (HD/4);
            ((float4*)vs)[i] = *((const float4*)(vin + ((size_t)bh * L + (size_t)p * T + tile) * HD) + dq);
        }
    }
    __syncthreads();

    float2* vs2 = (float2*)vs;
    #pragma unroll
    for (int step = 0; step < NE; step++) {
        const int e = ASC ? step : (NE - 1 - step);
        int s = 1;
        #pragma unroll
        for (int t2 = 0; t2 < NE; t2++) if (t2 < e) s *= BASE;
        const int eg = e + (INNER ? 0 : NE);
        size_t lvl = ((size_t)eg * NBH + bh) * (size_t)(L / BASE) * BB;
        for (int it = tid; it < GT * BB; it += 256) {
            int g = it / BB, c = it % BB;
            size_t gg = INNER ? ((size_t)tile * GT + g) : ((size_t)g * T + tile);
            as_[it] = attn[lvl + gg * BB + c];
        }
        __syncthreads();
        for (int w = tid; w < GT * HD2; w += 256) {
            int g = w >> 6, d = w & 63;
            int hi = g / s, lo = g - hi * s;
            int pb = hi * BASE * s + lo;
            float2 vv[BASE];
            #pragma unroll
            for (int j = 0; j < BASE; j++) vv[j] = vs2[(pb + j * s) * HD2 + d];
            const float* ag = as_ + g * BB;
            #pragma unroll
            for (int J = 0; J < BASE; J++) {
                float2 o = make_float2(0.f, 0.f);
                #pragma unroll
                for (int j = 0; j < BASE; j++) {
                    float a = ag[J * BASE + j];
                    o.x += a * vv[j].x;
                    o.y += a * vv[j].y;
                }
                vs2[(pb + J * s) * HD2 + d] = o;
            }
        }
        __syncthreads();
    }

    if (INNER) {
        size_t gb = ((size_t)bh * L + (size_t)tile * T) * HD;
        float4* v4 = (float4*)(vout + gb);
        for (int i = tid; i < T * HD / 4; i += 256) v4[i] = ((float4*)vs)[i];
    } else {
        for (int i = tid; i < T * (HD/4); i += 256) {
            int p = i / (HD/4), dq = i % (HD/4);
            *((float4*)(vout + ((size_t)bh * L + (size_t)p * T + tile) * HD) + dq) = ((float4*)vs)[i];
        }
    }
}

// ---------------------------------------------------------------------------
// FUSED: v2's final inner-desc stage pass + combine, all position-major.
// ---------------------------------------------------------------------------
template<int BASE, int T, int NE>
__launch_bounds__(256)
__global__ void stage_combine(const float* __restrict__ vin,
                              const float* __restrict__ wa,
                              const float* __restrict__ v0,
                              const float* __restrict__ attn,
                              const float* __restrict__ xres, int XRW,
                              const float* __restrict__ wpe, const float* __restrict__ spe,
                              const float* __restrict__ bpe,
                              float* __restrict__ yf, int YFW,
                              uint32_t* __restrict__ ytf, int YTW,
                              int L, int WV)
{
    constexpr int GT = T / BASE;
    constexpr int BB = BASE * BASE;
    constexpr int HD2 = HD / 2;
    extern __shared__ float sh[];
    float* vs  = sh;
    float* v0s = sh + T * HD;
    float* prm = v0s + (T + 2) * HD;
    float* as_ = prm + 5 * 128;

    const int tile = blockIdx.x, bh = blockIdx.y, tid = threadIdx.x;
    const int b = bh >> 3, h = bh & 7;

    {
        size_t gb = ((size_t)bh * L + (size_t)tile * T) * HD;
        const float4* v4 = (const float4*)(vin + gb);
        for (int i = tid; i < T * HD / 4; i += 256) ((float4*)vs)[i] = v4[i];
    }
    for (int i = tid; i < (T + 2) * (HD/4); i += 256) {
        int l = i >> 5, dq = i & 31;
        int lg = tile * T - 1 + l;
        float4 v = (lg >= 0 && lg < L)
            ? *((const float4*)(v0 + ((size_t)bh * L + lg) * HD) + dq)
            : make_float4(0.f, 0.f, 0.f, 0.f);
        ((float4*)v0s)[l * 32 + dq] = v;
    }
    if (tid < 128) {
        int c = h * HD + tid;
        prm[tid]       = wpe[c*3];
        prm[128 + tid] = wpe[c*3+1];
        prm[256 + tid] = wpe[c*3+2];
        prm[384 + tid] = spe[c];
        prm[512 + tid] = bpe[c];
    }
    __syncthreads();

    float2* vs2 = (float2*)vs;
    #pragma unroll
    for (int step = 0; step < NE; step++) {
        const int e = NE - 1 - step;
        int s = 1;
        #pragma unroll
        for (int t2 = 0; t2 < NE; t2++) if (t2 < e) s *= BASE;
        size_t lvl = ((size_t)e * NBH + bh) * (size_t)(L / BASE) * BB;
        for (int it = tid; it < GT * BB; it += 256) {
            int g = it / BB, c = it % BB;
            as_[it] = attn[lvl + ((size_t)tile * GT + g) * BB + c];
        }
        __syncthreads();
        for (int w = tid; w < GT * HD2; w += 256) {
            int g = w >> 6, d = w & 63;
            int hi = g / s, lo = g - hi * s;
            int pb = hi * BASE * s + lo;
            float2 vv[BASE];
            #pragma unroll
            for (int j = 0; j < BASE; j++) vv[j] = vs2[(pb + j * s) * HD2 + d];
            const float* ag = as_ + g * BB;
            #pragma unroll
            for (int J = 0; J < BASE; J++) {
                float2 o = make_float2(0.f, 0.f);
                #pragma unroll
                for (int j = 0; j < BASE; j++) {
                    float a = ag[J * BASE + j];
                    o.x += a * vv[j].x;
                    o.y += a * vv[j].y;
                }
                vs2[(pb + J * s) * HD2 + d] = o;
            }
        }
        __syncthreads();
    }

    const bool wf = (yf != nullptr);
    for (int i = tid; i < T * HD; i += 256) {
        int l = i >> 7, d = i & 127;
        int gl = tile * T + l;
        if (gl >= WV) continue;
        float pe = (prm[d] * v0s[l * HD + d] + prm[128 + d] * v0s[(l + 1) * HD + d]
                  + prm[256 + d] * v0s[(l + 2) * HD + d]) * prm[384 + d] + prm[512 + d];
        int c = h * HD + d;
        float val = xres[((size_t)b * XRW + gl) * C_DIM + c]
                  + vs[l * HD + d]
                  + wa[((size_t)bh * L + gl) * HD + d]
                  + pe;
        if (wf) yf[((size_t)b * YFW + gl) * C_DIM + c] = val;
        int kb = c >> 5;
        ytf[((size_t)b * YTW + gl) * C_DIM + (kb << 5) + kperm(c & 31)] = f2tf(val);
    }
}

// ---------------------------------------------------------------------------
extern "C" void kernel_launch(void* const* d_in, const int* in_sizes, int n_in,
                              void* d_out, int out_size)
{
    const float* x = (const float*)d_in[0];
    const float *wqk2=(const float*)d_in[1], *sqk2=(const float*)d_in[2], *bqk2=(const float*)d_in[3];
    const float *wv2 =(const float*)d_in[4], *sv2 =(const float*)d_in[5], *bv2 =(const float*)d_in[6];
    const float *wpe2=(const float*)d_in[7], *spe2=(const float*)d_in[8], *bpe2=(const float*)d_in[9];
    const float *wqk3=(const float*)d_in[10],*sqk3=(const float*)d_in[11],*bqk3=(const float*)d_in[12];
    const float *wv3 =(const float*)d_in[13],*sv3 =(const float*)d_in[14],*bv3 =(const float*)d_in[15];
    const float *wpe3=(const float*)d_in[16],*spe3=(const float*)d_in[17],*bpe3=(const float*)d_in[18];
    const float *wproj=(const float*)d_in[19],*sproj=(const float*)d_in[20],*bproj=(const float*)d_in[21];
    float* out = (float*)d_out;

    float *q, *k, *v0, *wa, *wb, *attn, *x1, *xf;
    uint32_t *xtf, *x1tf, *wp;
    cudaGetSymbolAddress((void**)&q,    g_q);
    cudaGetSymbolAddress((void**)&k,    g_k);
    cudaGetSymbolAddress((void**)&v0,   g_v0);
    cudaGetSymbolAddress((void**)&wa,   g_wa);
    cudaGetSymbolAddress((void**)&wb,   g_wb);
    cudaGetSymbolAddress((void**)&attn, g_attn);
    cudaGetSymbolAddress((void**)&x1,   g_x1);
    cudaGetSymbolAddress((void**)&xf,   g_xf);
    cudaGetSymbolAddress((void**)&xtf,  g_xtf);
    cudaGetSymbolAddress((void**)&x1tf, g_x1tf);
    cudaGetSymbolAddress((void**)&wp,   g_wp);

    const int SMEM = 135168;
    cudaFuncSetAttribute(gemm_tc<0>, cudaFuncAttributeMaxDynamicSharedMemorySize, SMEM);
    cudaFuncSetAttribute(gemm_tc<1>, cudaFuncAttributeMaxDynamicSharedMemorySize, SMEM);
    const int SC2 = (64*128 + 66*128 + 5*128 + 32*4) * 4;
    const int SC3 = (81*128 + 83*128 + 5*128 + 27*9) * 4;
    cudaFuncSetAttribute(stage_combine<2,64,6>, cudaFuncAttributeMaxDynamicSharedMemorySize, SC2);
    cudaFuncSetAttribute(stage_combine<3,81,4>, cudaFuncAttributeMaxDynamicSharedMemorySize, SC3);

    transpose_x<<<dim3(128, 32, 4), dim3(32, 8)>>>(x, xf, xtf);

    // ---- block 1: base=2, L=4096, NE=6, T=64 ----
    {
        const int L = L2C;
        conv_w<<<(2048 * 1024) / 256, 256>>>(wqk2, wv2, wp, 1024, 2048 * 1024);
        gemm_tc<0><<<dim3(32,8,4),256,SMEM>>>(xtf, W_LEN, wp, sqk2,bqk2, sv2,bv2, q,k,v0, L, W_LEN);
        attn_kernel<2,64,6,true ><<<dim3(64,NBH),256>>>(q,k,attn,L);
        attn_kernel<2,64,6,false><<<dim3(64,NBH),256>>>(q,k,attn,L);
        stage_kernel<2,64,6,true ,true ><<<dim3(64,NBH),256>>>(v0,wa,attn,L);
        stage_kernel<2,64,6,false,true ><<<dim3(64,NBH),256>>>(wa,wa,attn,L);
        stage_kernel<2,64,6,false,false><<<dim3(64,NBH),256>>>(v0,wb,attn,L);
        stage_combine<2,64,6><<<dim3(64,NBH),256,SC2>>>(wb, wa, v0, attn,
            xf, W_LEN, wpe2,spe2,bpe2, x1, W_LEN, x1tf, L3P, L, L);
    }
    // ---- block 2: base=3, L=6561, NE=4, T=81 ----
    {
        const int L = L3C;
        conv_w<<<(2048 * 1024) / 256, 256>>>(wqk3, wv3, wp, 1024, 2048 * 1024);
        gemm_tc<0><<<dim3(52,8,4),256,SMEM>>>(x1tf, L3P, wp, sqk3,bqk3, sv3,bv3, q,k,v0, L, W_LEN);
        attn_kernel<3,81,4,true ><<<dim3(81,NBH),256>>>(q,k,attn,L);
        attn_kernel<3,81,4,false><<<dim3(81,NBH),256>>>(q,k,attn,L);
        stage_kernel<3,81,4,true ,true ><<<dim3(81,NBH),256>>>(v0,wa,attn,L);
        stage_kernel<3,81,4,false,true ><<<dim3(81,NBH),256>>>(wa,wa,attn,L);
        stage_kernel<3,81,4,false,false><<<dim3(81,NBH),256>>>(v0,wb,attn,L);
        stage_combine<3,81,4><<<dim3(81,NBH),256,SC3>>>(wb, wa, v0, attn,
            x1, W_LEN, wpe3,spe3,bpe3, nullptr, 0, xtf, W_LEN, L, W_LEN);
    }
    // ---- final projection ----
    conv_w<<<(1024 * 1024) / 256, 256>>>(wproj, nullptr, wp, 1024, 1024 * 1024);
    gemm_tc<1><<<dim3(32,4,4),256,SMEM>>>(xtf, W_LEN, wp, sproj,bproj, nullptr,nullptr,
                                          out, nullptr, nullptr, W_LEN, W_LEN);
}

// round 15
// speedup vs baseline: 1.9718x; 1.3857x over previous
#include <cuda_runtime.h>
#include <cuda_fp16.h>
#include <cstdint>

#define C_DIM 1024
#define CW    512     // C_DIM/2 half2 words per row
#define B_SZ  4
#define W_LEN 4096
#define NHD   8
#define KD    64
#define HD    128
#define L2C   4096
#define L3C   6561
#define L3P   6656
#define NBH   (B_SZ*NHD)
#define SCALE 0.125f

__device__ float    g_q   [NBH * L3C * KD];
__device__ float    g_k   [NBH * L3C * KD];
__device__ float    g_v0  [NBH * L3C * HD];
__device__ float    g_wa  [NBH * L3C * HD];
__device__ float    g_wb  [NBH * L3C * HD];
__device__ float    g_attn[5038848];
__device__ float    g_xf  [B_SZ * W_LEN * C_DIM];   // x position-major f32
__device__ float    g_x1  [B_SZ * W_LEN * C_DIM];   // x1 position-major f32
__device__ uint32_t g_xh  [B_SZ * W_LEN * CW];      // fp16-pair pos-major (x, later x2)
__device__ uint32_t g_x1h [B_SZ * L3P  * CW];       // fp16-pair pos-major x1
__device__ uint32_t g_wp  [2048 * CW];              // fp16-pair k-permuted W

// word position of even channel c within a row of CW pair-words:
// chunk = 64 halfs; word 8ks+2q+r holds halfs {16ks+8r+2q, +1}
__device__ __forceinline__ int wordpos(int c) {   // c even, in [0, C_DIM)
    int kb = c >> 6, hk = c & 63;
    int ks = hk >> 4, rem = hk & 15;
    int r = rem >> 3, q = (rem & 7) >> 1;
    return (kb << 5) + (ks << 3) + (q << 1) + r;
}
__device__ __forceinline__ uint32_t pack2(float a, float b) {
    __half2 h = __floats2half2_rn(a, b);
    return *(uint32_t*)&h;
}

// ---------------------------------------------------------------------------
// Convert + merge + pair-permute weights into fp16 pair words.
// ---------------------------------------------------------------------------
__global__ void conv_w(const float* __restrict__ w0, const float* __restrict__ w1,
                       uint32_t* __restrict__ wp, int rows0, int total)
{
    int idx = blockIdx.x * 256 + threadIdx.x;
    if (idx >= total) return;
    int o = idx >> 9, w = idx & 511;
    int kb = w >> 5, wi = w & 31;
    int ks = wi >> 3, t = wi & 7, q = t >> 1, r = t & 1;
    int hk = (kb << 6) + (ks << 4) + (r << 3) + (q << 1);
    const float* src = (o < rows0) ? (w0 + (size_t)o * C_DIM)
                                   : (w1 + (size_t)(o - rows0) * C_DIM);
    wp[(size_t)o * CW + w] = pack2(src[hk], src[hk + 1]);
}

// ---------------------------------------------------------------------------
// x[b][c][l] -> pos-major: xf[b][l][c] (f32) and xh[b][l][wordpos(c)] (fp16)
// ---------------------------------------------------------------------------
__global__ void transpose_x(const float* __restrict__ x,
                            float* __restrict__ xf, uint32_t* __restrict__ xh)
{
    __shared__ float t[32][33];
    const int b = blockIdx.z, l0 = blockIdx.x * 32, c0 = blockIdx.y * 32;
    const int tx = threadIdx.x, ty = threadIdx.y;
    const int tid = ty * 32 + tx;
    #pragma unroll
    for (int j = 0; j < 4; j++)
        t[ty + 8*j][tx] = x[((size_t)b * C_DIM + c0 + ty + 8*j) * W_LEN + l0 + tx];
    __syncthreads();
    #pragma unroll
    for (int j = 0; j < 4; j++) {
        int l = l0 + ty + 8*j;
        xf[((size_t)b * W_LEN + l) * C_DIM + c0 + tx] = t[tx][ty + 8*j];
    }
    for (int i = tid; i < 32 * 16; i += 256) {
        int li = i >> 4, p = i & 15;
        int c = c0 + 2 * p;
        int w = wordpos(c);
        xh[((size_t)b * W_LEN + l0 + li) * CW + w] = pack2(t[2*p][li], t[2*p+1][li]);
    }
}

// ---------------------------------------------------------------------------
// fp16 mma.sync m16n8k16 GEMM. A = wp, B = xh (both pair-permuted, pos-major).
// 256x128 CTA tile, K-chunks of 64 halfs (32 words), 16 iterations.
// Fragment loads identical to the proven tf32 layout (stride 40, LDS.64,
// conflict-free). MODE 0: M=2048 qk/v scatter + bias fast path. MODE 1: proj.
// ---------------------------------------------------------------------------
template<int MODE>
__launch_bounds__(256)
__global__ void gemm_tc(const uint32_t* __restrict__ xh, int Lpad,
                        const uint32_t* __restrict__ wp,
                        const float* __restrict__ s0, const float* __restrict__ b0,
                        const float* __restrict__ s1, const float* __restrict__ b1,
                        float* __restrict__ qbuf, float* __restrict__ kbuf,
                        float* __restrict__ vbuf, int L, int WV)
{
    extern __shared__ float smf[];
    uint32_t* sm = (uint32_t*)smf;
    constexpr int STR = 40;
    uint32_t* Asm[2] = { sm,         sm + 10240 };
    uint32_t* Bsm[2] = { sm + 20480, sm + 25600 };

    const int tid  = threadIdx.x;
    const int lane = tid & 31, warp = tid >> 5;
    const int wm = warp >> 1, wn = warp & 1;
    const int grp = lane >> 2, qid = lane & 3;
    const int l0 = blockIdx.x * 128, o0 = blockIdx.y * 256, bz = blockIdx.z;

    const bool alt = (MODE == 0) && (o0 >= 1024);
    const float* sptr = alt ? (s1 + (o0 - 1024)) : (s0 + o0);
    const float* bptr = alt ? (b1 + (o0 - 1024)) : (b0 + o0);

    if (MODE == 0 && l0 >= WV) {
        for (int f = tid; f < 8192; f += 256) {
            int l = f >> 6, o4 = (f & 63) << 2;
            int lgl = l0 + l;
            if (lgl >= L) continue;
            float4 r = *(const float4*)(bptr + o4);
            int og = o0 + o4;
            float* dst;
            if (o0 < 1024) {
                int h = og >> 7, rr = (og >> 6) & 1, d0 = og & 63;
                dst = (rr ? kbuf : qbuf) + ((size_t)(bz * NHD + h) * L + lgl) * KD + d0;
            } else {
                int oc = og - 1024, h = oc >> 7, d0 = oc & 127;
                dst = vbuf + ((size_t)(bz * NHD + h) * L + lgl) * HD + d0;
            }
            *(float4*)dst = r;
        }
        return;
    }

    const int am = tid >> 3, ak = (tid & 7) * 4;
    const uint32_t* arow = wp + (size_t)(o0 + am) * CW + ak;
    const uint32_t* brow = xh + ((size_t)bz * Lpad + l0 + am) * CW + ak;

    float acc[4][8][4] = {};

    auto load_tile = [&](int buf, int c0w) {
        #pragma unroll
        for (int i = 0; i < 8; i++) {
            uint32_t d = (uint32_t)__cvta_generic_to_shared(&Asm[buf][(am + 32*i) * STR + ak]);
            const uint32_t* s = arow + (size_t)(32*i) * CW + c0w;
            asm volatile("cp.async.ca.shared.global [%0], [%1], 16;\n" :: "r"(d), "l"(s));
        }
        #pragma unroll
        for (int i = 0; i < 4; i++) {
            uint32_t d = (uint32_t)__cvta_generic_to_shared(&Bsm[buf][(am + 32*i) * STR + ak]);
            const uint32_t* s = brow + (size_t)(32*i) * CW + c0w;
            asm volatile("cp.async.ca.shared.global [%0], [%1], 16;\n" :: "r"(d), "l"(s));
        }
        asm volatile("cp.async.commit_group;\n");
    };

    load_tile(0, 0);
    for (int kt = 0; kt < 16; ++kt) {
        asm volatile("cp.async.wait_group 0;\n");
        __syncthreads();
        if (kt + 1 < 16) load_tile((kt + 1) & 1, (kt + 1) * 32);
        const uint32_t* Ab = Asm[kt & 1];
        const uint32_t* Bb = Bsm[kt & 1];

        #pragma unroll
        for (int ks = 0; ks < 4; ++ks) {
            uint32_t bf[8][2];
            #pragma unroll
            for (int nt = 0; nt < 8; ++nt) {
                uint2 bb = *(const uint2*)&Bb[(wn*64 + nt*8 + grp) * STR + ks*8 + qid*2];
                bf[nt][0] = bb.x; bf[nt][1] = bb.y;
            }
            #pragma unroll
            for (int mt = 0; mt < 4; ++mt) {
                const int base = (wm*64 + mt*16 + grp) * STR + ks*8 + qid*2;
                uint2 lo = *(const uint2*)&Ab[base];           // a0, a2
                uint2 hi = *(const uint2*)&Ab[base + 8*STR];   // a1, a3
                #pragma unroll
                for (int nt = 0; nt < 8; ++nt) {
                    float* d = acc[mt][nt];
                    asm volatile(
                        "mma.sync.aligned.m16n8k16.row.col.f32.f16.f16.f32 "
                        "{%0,%1,%2,%3},{%4,%5,%6,%7},{%8,%9},{%0,%1,%2,%3};\n"
                        : "+f"(d[0]), "+f"(d[1]), "+f"(d[2]), "+f"(d[3])
                        : "r"(lo.x), "r"(hi.x), "r"(lo.y), "r"(hi.y),
                          "r"(bf[nt][0]), "r"(bf[nt][1]));
                }
            }
        }
        __syncthreads();
    }

    float* ep = smf;
    constexpr int EPS = (MODE == 0) ? 260 : 132;
    #pragma unroll
    for (int mt = 0; mt < 4; ++mt)
        #pragma unroll
        for (int nt = 0; nt < 8; ++nt) {
            int ol = wm*64 + mt*16 + grp;
            int ll = wn*64 + nt*8 + 2*qid;
            float* c = acc[mt][nt];
            if (MODE == 0) {
                ep[ll * EPS + ol]           = c[0];
                ep[(ll + 1) * EPS + ol]     = c[1];
                ep[ll * EPS + ol + 8]       = c[2];
                ep[(ll + 1) * EPS + ol + 8] = c[3];
            } else {
                ep[ol * EPS + ll]           = c[0];
                ep[ol * EPS + ll + 1]       = c[1];
                ep[(ol + 8) * EPS + ll]     = c[2];
                ep[(ol + 8) * EPS + ll + 1] = c[3];
            }
        }
    __syncthreads();

    if (MODE == 0) {
        for (int f = tid; f < 8192; f += 256) {
            int l = f >> 6, o4 = (f & 63) << 2;
            int lgl = l0 + l;
            if (lgl >= L) continue;
            float4 v  = *(float4*)&ep[l * EPS + o4];
            float4 s4 = *(const float4*)(sptr + o4);
            float4 b4 = *(const float4*)(bptr + o4);
            float4 r = make_float4(v.x*s4.x + b4.x, v.y*s4.y + b4.y,
                                   v.z*s4.z + b4.z, v.w*s4.w + b4.w);
            int og = o0 + o4;
            float* dst;
            if (o0 < 1024) {
                int h = og >> 7, rr = (og >> 6) & 1, d0 = og & 63;
                dst = (rr ? kbuf : qbuf) + ((size_t)(bz * NHD + h) * L + lgl) * KD + d0;
            } else {
                int oc = og - 1024, h = oc >> 7, d0 = oc & 127;
                dst = vbuf + ((size_t)(bz * NHD + h) * L + lgl) * HD + d0;
            }
            *(float4*)dst = r;
        }
    } else {
        for (int f = tid; f < 8192; f += 256) {
            int o = f >> 5, l4 = (f & 31) << 2;
            float4 v = *(float4*)&ep[o * EPS + l4];
            float sc = sptr[o], bi = bptr[o];
            float4 r = make_float4(v.x*sc + bi, v.y*sc + bi, v.z*sc + bi, v.w*sc + bi);
            *(float4*)(qbuf + ((size_t)(bz * C_DIM + o0 + o)) * W_LEN + l0 + l4) = r;
        }
    }
}

// ---------------------------------------------------------------------------
// Attention matrices (R13 conflict-free stride-68 version, unchanged).
// ---------------------------------------------------------------------------
template<int BASE, int T, int NE, bool INNER>
__launch_bounds__(256)
__global__ void attn_kernel(const float* __restrict__ q, const float* __restrict__ k,
                            float* __restrict__ attn, int L)
{
    constexpr int GT = T / BASE;
    constexpr int BB = BASE * BASE;
    constexpr int QSTR = KD + 4;
    __shared__ float qs[T * QSTR];
    __shared__ float ks[T * QSTR];
    __shared__ float ls[GT * BB];
    const int tile = blockIdx.x, bh = blockIdx.y, tid = threadIdx.x;

    for (int i = tid; i < T * (KD/4); i += 256) {
        int p = i >> 4, dq = i & 15;
        size_t gb;
        if (INNER) gb = ((size_t)bh * L + (size_t)tile * T + p) * KD;
        else       gb = ((size_t)bh * L + (size_t)p * T + tile) * KD;
        *(float4*)(qs + p * QSTR + dq * 4) = *((const float4*)(q + gb) + dq);
        *(float4*)(ks + p * QSTR + dq * 4) = *((const float4*)(k + gb) + dq);
    }
    __syncthreads();

    int s = 1;
    #pragma unroll
    for (int e = 0; e < NE; e++) {
        for (int it = tid; it < GT * BB; it += 256) {
            int g = it / BB, rem = it % BB;
            int J = rem / BASE, j = rem % BASE;
            int hi = g / s, lo = g % s;
            int pJ = hi * BASE * s + J * s + lo;
            int pj = hi * BASE * s + j * s + lo;
            const float4* qp = (const float4*)(qs + pj * QSTR);
            const float4* kp = (const float4*)(ks + pJ * QSTR);
            float dot = 0.f;
            #pragma unroll
            for (int dd = 0; dd < KD/4; dd++) {
                float4 a = qp[dd], b2 = kp[dd];
                dot += a.x*b2.x + a.y*b2.y + a.z*b2.z + a.w*b2.w;
            }
            ls[it] = dot * SCALE;
        }
        __syncthreads();
        const int eg = e + (INNER ? 0 : NE);
        size_t lvl = ((size_t)eg * NBH + bh) * (size_t)(L / BASE) * BB;
        for (int it = tid; it < GT * BASE; it += 256) {
            int g = it / BASE, J = it % BASE;
            const float* lg2 = ls + (g * BASE + J) * BASE;
            float m = lg2[0];
            #pragma unroll
            for (int j = 1; j < BASE; j++) m = fmaxf(m, lg2[j]);
            float ex[BASE]; float sum = 0.f;
            #pragma unroll
            for (int j = 0; j < BASE; j++) { ex[j] = __expf(lg2[j] - m); sum += ex[j]; }
            float inv = 1.f / sum;
            size_t gg = INNER ? ((size_t)tile * GT + g) : ((size_t)g * T + tile);
            float* ap = attn + lvl + gg * BB + (size_t)J * BASE;
            #pragma unroll
            for (int j = 0; j < BASE; j++) ap[j] = ex[j] * inv;
        }
        __syncthreads();
        s *= BASE;
    }
}

// ---------------------------------------------------------------------------
// Apply NE levels to v inside SMEM (float2-vectorized, unchanged).
// ---------------------------------------------------------------------------
template<int BASE, int T, int NE, bool INNER, bool ASC>
__launch_bounds__(256)
__global__ void stage_kernel(const float* __restrict__ vin, float* __restrict__ vout,
                             const float* __restrict__ attn, int L)
{
    constexpr int GT = T / BASE;
    constexpr int BB = BASE * BASE;
    constexpr int HD2 = HD / 2;
    __shared__ float vs[T * HD];
    __shared__ float as_[GT * BB];
    const int tile = blockIdx.x, bh = blockIdx.y, tid = threadIdx.x;

    if (INNER) {
        size_t gb = ((size_t)bh * L + (size_t)tile * T) * HD;
        const float4* v4 = (const float4*)(vin + gb);
        for (int i = tid; i < T * HD / 4; i += 256) ((float4*)vs)[i] = v4[i];
    } else {
        for (int i = tid; i < T * (HD/4); i += 256) {
            int p = i / (HD/4), dq = i % (HD/4);
            ((float4*)vs)[i] = *((const float4*)(vin + ((size_t)bh * L + (size_t)p * T + tile) * HD) + dq);
        }
    }
    __syncthreads();

    float2* vs2 = (float2*)vs;
    #pragma unroll
    for (int step = 0; step < NE; step++) {
        const int e = ASC ? step : (NE - 1 - step);
        int s = 1;
        #pragma unroll
        for (int t2 = 0; t2 < NE; t2++) if (t2 < e) s *= BASE;
        const int eg = e + (INNER ? 0 : NE);
        size_t lvl = ((size_t)eg * NBH + bh) * (size_t)(L / BASE) * BB;
        for (int it = tid; it < GT * BB; it += 256) {
            int g = it / BB, c = it % BB;
            size_t gg = INNER ? ((size_t)tile * GT + g) : ((size_t)g * T + tile);
            as_[it] = attn[lvl + gg * BB + c];
        }
        __syncthreads();
        for (int w = tid; w < GT * HD2; w += 256) {
            int g = w >> 6, d = w & 63;
            int hi = g / s, lo = g - hi * s;
            int pb = hi * BASE * s + lo;
            float2 vv[BASE];
            #pragma unroll
            for (int j = 0; j < BASE; j++) vv[j] = vs2[(pb + j * s) * HD2 + d];
            const float* ag = as_ + g * BB;
            #pragma unroll
            for (int J = 0; J < BASE; J++) {
                float2 o = make_float2(0.f, 0.f);
                #pragma unroll
                for (int j = 0; j < BASE; j++) {
                    float a = ag[J * BASE + j];
                    o.x += a * vv[j].x;
                    o.y += a * vv[j].y;
                }
                vs2[(pb + J * s) * HD2 + d] = o;
            }
        }
        __syncthreads();
    }

    if (INNER) {
        size_t gb = ((size_t)bh * L + (size_t)tile * T) * HD;
        float4* v4 = (float4*)(vout + gb);
        for (int i = tid; i < T * HD / 4; i += 256) v4[i] = ((float4*)vs)[i];
    } else {
        for (int i = tid; i < T * (HD/4); i += 256) {
            int p = i / (HD/4), dq = i % (HD/4);
            *((float4*)(vout + ((size_t)bh * L + (size_t)p * T + tile) * HD) + dq) = ((float4*)vs)[i];
        }
    }
}

// ---------------------------------------------------------------------------
// FUSED: v2's final inner-desc stage pass + combine; fp16-pair output.
// ---------------------------------------------------------------------------
template<int BASE, int T, int NE>
__launch_bounds__(256)
__global__ void stage_combine(const float* __restrict__ vin,
                              const float* __restrict__ wa,
                              const float* __restrict__ v0,
                              const float* __restrict__ attn,
                              const float* __restrict__ xres, int XRW,
                              const float* __restrict__ wpe, const float* __restrict__ spe,
                              const float* __restrict__ bpe,
                              float* __restrict__ yf, int YFW,
                              uint32_t* __restrict__ yh, int YHW,
                              int L, int WV)
{
    constexpr int GT = T / BASE;
    constexpr int BB = BASE * BASE;
    constexpr int HD2 = HD / 2;
    extern __shared__ float sh[];
    float* vs  = sh;
    float* v0s = sh + T * HD;
    float* prm = v0s + (T + 2) * HD;
    float* as_ = prm + 5 * 128;

    const int tile = blockIdx.x, bh = blockIdx.y, tid = threadIdx.x;
    const int b = bh >> 3, h = bh & 7;

    {
        size_t gb = ((size_t)bh * L + (size_t)tile * T) * HD;
        const float4* v4 = (const float4*)(vin + gb);
        for (int i = tid; i < T * HD / 4; i += 256) ((float4*)vs)[i] = v4[i];
    }
    for (int i = tid; i < (T + 2) * (HD/4); i += 256) {
        int l = i >> 5, dq = i & 31;
        int lg = tile * T - 1 + l;
        float4 v = (lg >= 0 && lg < L)
            ? *((const float4*)(v0 + ((size_t)bh * L + lg) * HD) + dq)
            : make_float4(0.f, 0.f, 0.f, 0.f);
        ((float4*)v0s)[l * 32 + dq] = v;
    }
    if (tid < 128) {
        int c = h * HD + tid;
        prm[tid]       = wpe[c*3];
        prm[128 + tid] = wpe[c*3+1];
        prm[256 + tid] = wpe[c*3+2];
        prm[384 + tid] = spe[c];
        prm[512 + tid] = bpe[c];
    }
    __syncthreads();

    float2* vs2 = (float2*)vs;
    #pragma unroll
    for (int step = 0; step < NE; step++) {
        const int e = NE - 1 - step;
        int s = 1;
        #pragma unroll
        for (int t2 = 0; t2 < NE; t2++) if (t2 < e) s *= BASE;
        size_t lvl = ((size_t)e * NBH + bh) * (size_t)(L / BASE) * BB;
        for (int it = tid; it < GT * BB; it += 256) {
            int g = it / BB, c = it % BB;
            as_[it] = attn[lvl + ((size_t)tile * GT + g) * BB + c];
        }
        __syncthreads();
        for (int w = tid; w < GT * HD2; w += 256) {
            int g = w >> 6, d = w & 63;
            int hi = g / s, lo = g - hi * s;
            int pb = hi * BASE * s + lo;
            float2 vv[BASE];
            #pragma unroll
            for (int j = 0; j < BASE; j++) vv[j] = vs2[(pb + j * s) * HD2 + d];
            const float* ag = as_ + g * BB;
            #pragma unroll
            for (int J = 0; J < BASE; J++) {
                float2 o = make_float2(0.f, 0.f);
                #pragma unroll
                for (int j = 0; j < BASE; j++) {
                    float a = ag[J * BASE + j];
                    o.x += a * vv[j].x;
                    o.y += a * vv[j].y;
                }
                vs2[(pb + J * s) * HD2 + d] = o;
            }
        }
        __syncthreads();
    }

    const bool wf = (yf != nullptr);
    for (int i = tid; i < T * HD2; i += 256) {
        int l = i >> 6, dp = i & 63;
        int gl = tile * T + l;
        if (gl >= WV) continue;
        int d0 = 2 * dp;
        float val[2];
        #pragma unroll
        for (int u = 0; u < 2; u++) {
            int d = d0 + u;
            float pe = (prm[d] * v0s[l * HD + d] + prm[128 + d] * v0s[(l + 1) * HD + d]
                      + prm[256 + d] * v0s[(l + 2) * HD + d]) * prm[384 + d] + prm[512 + d];
            int c = h * HD + d;
            val[u] = xres[((size_t)b * XRW + gl) * C_DIM + c]
                   + vs[l * HD + d]
                   + wa[((size_t)bh * L + gl) * HD + d]
                   + pe;
        }
        int c0 = h * HD + d0;
        if (wf) *(float2*)&yf[((size_t)b * YFW + gl) * C_DIM + c0] = make_float2(val[0], val[1]);
        yh[((size_t)b * YHW + gl) * CW + wordpos(c0)] = pack2(val[0], val[1]);
    }
}

// ---------------------------------------------------------------------------
extern "C" void kernel_launch(void* const* d_in, const int* in_sizes, int n_in,
                              void* d_out, int out_size)
{
    const float* x = (const float*)d_in[0];
    const float *wqk2=(const float*)d_in[1], *sqk2=(const float*)d_in[2], *bqk2=(const float*)d_in[3];
    const float *wv2 =(const float*)d_in[4], *sv2 =(const float*)d_in[5], *bv2 =(const float*)d_in[6];
    const float *wpe2=(const float*)d_in[7], *spe2=(const float*)d_in[8], *bpe2=(const float*)d_in[9];
    const float *wqk3=(const float*)d_in[10],*sqk3=(const float*)d_in[11],*bqk3=(const float*)d_in[12];
    const float *wv3 =(const float*)d_in[13],*sv3 =(const float*)d_in[14],*bv3 =(const float*)d_in[15];
    const float *wpe3=(const float*)d_in[16],*spe3=(const float*)d_in[17],*bpe3=(const float*)d_in[18];
    const float *wproj=(const float*)d_in[19],*sproj=(const float*)d_in[20],*bproj=(const float*)d_in[21];
    float* out = (float*)d_out;

    float *q, *k, *v0, *wa, *wb, *attn, *x1, *xf;
    uint32_t *xh, *x1h, *wp;
    cudaGetSymbolAddress((void**)&q,    g_q);
    cudaGetSymbolAddress((void**)&k,    g_k);
    cudaGetSymbolAddress((void**)&v0,   g_v0);
    cudaGetSymbolAddress((void**)&wa,   g_wa);
    cudaGetSymbolAddress((void**)&wb,   g_wb);
    cudaGetSymbolAddress((void**)&attn, g_attn);
    cudaGetSymbolAddress((void**)&x1,   g_x1);
    cudaGetSymbolAddress((void**)&xf,   g_xf);
    cudaGetSymbolAddress((void**)&xh,   g_xh);
    cudaGetSymbolAddress((void**)&x1h,  g_x1h);
    cudaGetSymbolAddress((void**)&wp,   g_wp);

    const int SMEM = 135168;
    cudaFuncSetAttribute(gemm_tc<0>, cudaFuncAttributeMaxDynamicSharedMemorySize, SMEM);
    cudaFuncSetAttribute(gemm_tc<1>, cudaFuncAttributeMaxDynamicSharedMemorySize, SMEM);
    const int SC2 = (64*128 + 66*128 + 5*128 + 32*4) * 4;
    const int SC3 = (81*128 + 83*128 + 5*128 + 27*9) * 4;
    cudaFuncSetAttribute(stage_combine<2,64,6>, cudaFuncAttributeMaxDynamicSharedMemorySize, SC2);
    cudaFuncSetAttribute(stage_combine<3,81,4>, cudaFuncAttributeMaxDynamicSharedMemorySize, SC3);

    transpose_x<<<dim3(128, 32, 4), dim3(32, 8)>>>(x, xf, xh);

    // ---- block 1: base=2, L=4096, NE=6, T=64 ----
    {
        const int L = L2C;
        conv_w<<<(2048 * CW) / 256, 256>>>(wqk2, wv2, wp, 1024, 2048 * CW);
        gemm_tc<0><<<dim3(32,8,4),256,SMEM>>>(xh, W_LEN, wp, sqk2,bqk2, sv2,bv2, q,k,v0, L, W_LEN);
        attn_kernel<2,64,6,true ><<<dim3(64,NBH),256>>>(q,k,attn,L);
        attn_kernel<2,64,6,false><<<dim3(64,NBH),256>>>(q,k,attn,L);
        stage_kernel<2,64,6,true ,true ><<<dim3(64,NBH),256>>>(v0,wa,attn,L);
        stage_kernel<2,64,6,false,true ><<<dim3(64,NBH),256>>>(wa,wa,attn,L);
        stage_kernel<2,64,6,false,false><<<dim3(64,NBH),256>>>(v0,wb,attn,L);
        stage_combine<2,64,6><<<dim3(64,NBH),256,SC2>>>(wb, wa, v0, attn,
            xf, W_LEN, wpe2,spe2,bpe2, x1, W_LEN, x1h, L3P, L, L);
    }
    // ---- block 2: base=3, L=6561, NE=4, T=81 ----
    {
        const int L = L3C;
        conv_w<<<(2048 * CW) / 256, 256>>>(wqk3, wv3, wp, 1024, 2048 * CW);
        gemm_tc<0><<<dim3(52,8,4),256,SMEM>>>(x1h, L3P, wp, sqk3,bqk3, sv3,bv3, q,k,v0, L, W_LEN);
        attn_kernel<3,81,4,true ><<<dim3(81,NBH),256>>>(q,k,attn,L);
        attn_kernel<3,81,4,false><<<dim3(81,NBH),256>>>(q,k,attn,L);
        stage_kernel<3,81,4,true ,true ><<<dim3(81,NBH),256>>>(v0,wa,attn,L);
        stage_kernel<3,81,4,false,true ><<<dim3(81,NBH),256>>>(wa,wa,attn,L);
        stage_kernel<3,81,4,false,false><<<dim3(81,NBH),256>>>(v0,wb,attn,L);
        stage_combine<3,81,4><<<dim3(81,NBH),256,SC3>>>(wb, wa, v0, attn,
            x1, W_LEN, wpe3,spe3,bpe3, nullptr, 0, xh, W_LEN, L, W_LEN);
    }
    // ---- final projection ----
    conv_w<<<(1024 * CW) / 256, 256>>>(wproj, nullptr, wp, 1024, 1024 * CW);
    gemm_tc<1><<<dim3(32,4,4),256,SMEM>>>(xh, W_LEN, wp, sproj,bproj, nullptr,nullptr,
                                          out, nullptr, nullptr, W_LEN, W_LEN);
}